// round 1
// baseline (speedup 1.0000x reference)
#include <cuda_runtime.h>
#include <math.h>

#define BB 4
#define SS 2048
#define EE 1024
#define HH 16
#define DKK 64
#define MM (BB*SS)      /* 8192 */
#define NN (HH*DKK)     /* 1024 */
#define KK EE           /* 1024 */

// Scratch (device globals — no allocation allowed in kernel_launch)
__device__ float g_Q[(size_t)BB*HH*SS*DKK];
__device__ float g_K[(size_t)BB*HH*SS*DKK];
__device__ float g_V[(size_t)BB*HH*SS*DKK];
__device__ float g_ctx[(size_t)MM*NN];

// ---------------------------------------------------------------------------
// GEMM: out = X(M,K) @ W(K,N) + bias(N)
// MODE 0: write split-head layout out[((b*H+h)*S+s)*DK+d]
// MODE 1: write row-major out[m*N+n]
// ---------------------------------------------------------------------------
template <int MODE>
__global__ __launch_bounds__(256) void gemm_bias_kernel(
    const float* __restrict__ X, const float* __restrict__ W,
    const float* __restrict__ bias, float* __restrict__ out)
{
    constexpr int BM = 128, BN = 128, BK = 16;
    __shared__ float As[BK][BM];      // As[k][m] (transposed X tile)
    __shared__ float Bs[BK][BN + 4];  // Bs[k][n]

    const int tid = threadIdx.x;
    const int m0 = blockIdx.y * BM;
    const int n0 = blockIdx.x * BN;

    float acc[8][8];
#pragma unroll
    for (int i = 0; i < 8; i++)
#pragma unroll
        for (int j = 0; j < 8; j++) acc[i][j] = 0.0f;

    const int ar = tid >> 2;          // 0..63
    const int ac = (tid & 3) * 4;     // 0,4,8,12
    const int br = tid >> 5;          // 0..7
    const int bc = (tid & 31) * 4;    // 0..124

    const int tm0 = (tid >> 4) * 8;
    const int tn0 = (tid & 15) * 8;

    for (int kt = 0; kt < KK; kt += BK) {
#pragma unroll
        for (int i = 0; i < 2; i++) {
            int row = ar + i * 64;
            float4 v = *(const float4*)(X + (size_t)(m0 + row) * KK + kt + ac);
            As[ac + 0][row] = v.x;
            As[ac + 1][row] = v.y;
            As[ac + 2][row] = v.z;
            As[ac + 3][row] = v.w;
        }
#pragma unroll
        for (int i = 0; i < 2; i++) {
            int row = br + i * 8;
            float4 v = *(const float4*)(W + (size_t)(kt + row) * NN + n0 + bc);
            *(float4*)&Bs[row][bc] = v;
        }
        __syncthreads();

#pragma unroll
        for (int k = 0; k < BK; k++) {
            float4 a0 = *(float4*)&As[k][tm0];
            float4 a1 = *(float4*)&As[k][tm0 + 4];
            float4 b0 = *(float4*)&Bs[k][tn0];
            float4 b1 = *(float4*)&Bs[k][tn0 + 4];
            float a[8] = {a0.x, a0.y, a0.z, a0.w, a1.x, a1.y, a1.z, a1.w};
            float b[8] = {b0.x, b0.y, b0.z, b0.w, b1.x, b1.y, b1.z, b1.w};
#pragma unroll
            for (int i = 0; i < 8; i++)
#pragma unroll
                for (int j = 0; j < 8; j++)
                    acc[i][j] = fmaf(a[i], b[j], acc[i][j]);
        }
        __syncthreads();
    }

#pragma unroll
    for (int i = 0; i < 8; i++) {
        int m = m0 + tm0 + i;
        int b = m >> 11;          // m / S
        int s = m & (SS - 1);     // m % S
#pragma unroll
        for (int j = 0; j < 8; j++) {
            int n = n0 + tn0 + j;
            float v = acc[i][j] + bias[n];
            if (MODE == 0) {
                int h = n >> 6;   // n / DK
                int d = n & 63;   // n % DK
                out[(((size_t)b * HH + h) * SS + s) * DKK + d] = v;
            } else {
                out[(size_t)m * NN + n] = v;
            }
        }
    }
}

// ---------------------------------------------------------------------------
// Flash attention: per block = (q-tile 64 rows, head h, batch b)
// online softmax, P*V accumulated in registers (4x4 per thread)
// ---------------------------------------------------------------------------
#define PITCH 68

__global__ __launch_bounds__(256) void attn_kernel(
    const float* __restrict__ Q, const float* __restrict__ K,
    const float* __restrict__ V, float* __restrict__ O)
{
    extern __shared__ float sm[];
    float (*Qs)[PITCH] = (float(*)[PITCH])(sm);
    float (*Ks)[PITCH] = (float(*)[PITCH])(sm + 64 * PITCH);
    float (*Vs)[PITCH] = (float(*)[PITCH])(sm + 2 * 64 * PITCH);
    float (*Ps)[PITCH] = (float(*)[PITCH])(sm + 3 * 64 * PITCH);

    const int tid = threadIdx.x;
    const int b = blockIdx.z, h = blockIdx.y;
    const int q0 = blockIdx.x * 64;
    const size_t base = ((size_t)b * HH + h) * SS * DKK;

    const float scale = 0.125f;  // 1/sqrt(64)

    // Load Q tile (scaled)
    for (int i = tid; i < 64 * 16; i += 256) {
        int r = i >> 4, c = (i & 15) * 4;
        float4 v = *(const float4*)(Q + base + (size_t)(q0 + r) * DKK + c);
        v.x *= scale; v.y *= scale; v.z *= scale; v.w *= scale;
        *(float4*)&Qs[r][c] = v;
    }

    const int tm0 = (tid >> 4) * 4;
    const int tn0 = (tid & 15) * 4;

    float o[4][4];
#pragma unroll
    for (int i = 0; i < 4; i++)
#pragma unroll
        for (int j = 0; j < 4; j++) o[i][j] = 0.0f;
    float mrow[4] = {-INFINITY, -INFINITY, -INFINITY, -INFINITY};
    float lrow[4] = {0.f, 0.f, 0.f, 0.f};

    for (int kt = 0; kt < SS; kt += 64) {
        __syncthreads();  // protect Ks/Vs/Ps from previous iteration's readers
        for (int i = tid; i < 64 * 16; i += 256) {
            int r = i >> 4, c = (i & 15) * 4;
            *(float4*)&Ks[r][c] = *(const float4*)(K + base + (size_t)(kt + r) * DKK + c);
            *(float4*)&Vs[r][c] = *(const float4*)(V + base + (size_t)(kt + r) * DKK + c);
        }
        __syncthreads();

        // S = Q @ K^T (4x4 per thread)
        float s[4][4];
#pragma unroll
        for (int i = 0; i < 4; i++)
#pragma unroll
            for (int j = 0; j < 4; j++) s[i][j] = 0.0f;

#pragma unroll 4
        for (int d = 0; d < 64; d += 4) {
            float4 a[4], bb[4];
#pragma unroll
            for (int i = 0; i < 4; i++) a[i] = *(float4*)&Qs[tm0 + i][d];
#pragma unroll
            for (int j = 0; j < 4; j++) bb[j] = *(float4*)&Ks[tn0 + j][d];
#pragma unroll
            for (int i = 0; i < 4; i++)
#pragma unroll
                for (int j = 0; j < 4; j++) {
                    s[i][j] = fmaf(a[i].x, bb[j].x, s[i][j]);
                    s[i][j] = fmaf(a[i].y, bb[j].y, s[i][j]);
                    s[i][j] = fmaf(a[i].z, bb[j].z, s[i][j]);
                    s[i][j] = fmaf(a[i].w, bb[j].w, s[i][j]);
                }
        }

        // online softmax per row (16 lanes per row, xor-shuffle reduce)
#pragma unroll
        for (int i = 0; i < 4; i++) {
            float mx = fmaxf(fmaxf(s[i][0], s[i][1]), fmaxf(s[i][2], s[i][3]));
#pragma unroll
            for (int off = 1; off < 16; off <<= 1)
                mx = fmaxf(mx, __shfl_xor_sync(0xffffffffu, mx, off));
            float mnew = fmaxf(mrow[i], mx);
            float alpha = __expf(mrow[i] - mnew);
            float ps = 0.f;
#pragma unroll
            for (int j = 0; j < 4; j++) {
                s[i][j] = __expf(s[i][j] - mnew);
                ps += s[i][j];
            }
#pragma unroll
            for (int off = 1; off < 16; off <<= 1)
                ps += __shfl_xor_sync(0xffffffffu, ps, off);
            lrow[i] = lrow[i] * alpha + ps;
            mrow[i] = mnew;
#pragma unroll
            for (int d = 0; d < 4; d++) o[i][d] *= alpha;
        }

        // store P
#pragma unroll
        for (int i = 0; i < 4; i++) {
            float4 pv = make_float4(s[i][0], s[i][1], s[i][2], s[i][3]);
            *(float4*)&Ps[tm0 + i][tn0] = pv;
        }
        __syncthreads();

        // O += P @ V
#pragma unroll 4
        for (int j = 0; j < 64; j += 4) {
            float4 p[4];
#pragma unroll
            for (int i = 0; i < 4; i++) p[i] = *(float4*)&Ps[tm0 + i][j];
            float4 v0 = *(float4*)&Vs[j + 0][tn0];
            float4 v1 = *(float4*)&Vs[j + 1][tn0];
            float4 v2 = *(float4*)&Vs[j + 2][tn0];
            float4 v3 = *(float4*)&Vs[j + 3][tn0];
#pragma unroll
            for (int i = 0; i < 4; i++) {
                o[i][0] = fmaf(p[i].x, v0.x, o[i][0]);
                o[i][1] = fmaf(p[i].x, v0.y, o[i][1]);
                o[i][2] = fmaf(p[i].x, v0.z, o[i][2]);
                o[i][3] = fmaf(p[i].x, v0.w, o[i][3]);
                o[i][0] = fmaf(p[i].y, v1.x, o[i][0]);
                o[i][1] = fmaf(p[i].y, v1.y, o[i][1]);
                o[i][2] = fmaf(p[i].y, v1.z, o[i][2]);
                o[i][3] = fmaf(p[i].y, v1.w, o[i][3]);
                o[i][0] = fmaf(p[i].z, v2.x, o[i][0]);
                o[i][1] = fmaf(p[i].z, v2.y, o[i][1]);
                o[i][2] = fmaf(p[i].z, v2.z, o[i][2]);
                o[i][3] = fmaf(p[i].z, v2.w, o[i][3]);
                o[i][0] = fmaf(p[i].w, v3.x, o[i][0]);
                o[i][1] = fmaf(p[i].w, v3.y, o[i][1]);
                o[i][2] = fmaf(p[i].w, v3.z, o[i][2]);
                o[i][3] = fmaf(p[i].w, v3.w, o[i][3]);
            }
        }
    }

    // epilogue: normalize and write ctx in [b][s][h][d] layout
#pragma unroll
    for (int i = 0; i < 4; i++) {
        float inv = 1.0f / lrow[i];
        int s_idx = q0 + tm0 + i;
        float4 v = make_float4(o[i][0] * inv, o[i][1] * inv, o[i][2] * inv, o[i][3] * inv);
        *(float4*)&O[(((size_t)b * SS + s_idx) * HH + h) * DKK + tn0] = v;
    }
}

// ---------------------------------------------------------------------------
extern "C" void kernel_launch(void* const* d_in, const int* in_sizes, int n_in,
                              void* d_out, int out_size)
{
    const float* x  = (const float*)d_in[0];
    const float* Wq = (const float*)d_in[1];
    const float* bq = (const float*)d_in[2];
    const float* Wk = (const float*)d_in[3];
    const float* bk = (const float*)d_in[4];
    const float* Wv = (const float*)d_in[5];
    const float* bv = (const float*)d_in[6];
    const float* Wo = (const float*)d_in[7];
    const float* bo = (const float*)d_in[8];
    float* out = (float*)d_out;

    float *Qp, *Kp, *Vp, *Cp;
    cudaGetSymbolAddress((void**)&Qp, g_Q);
    cudaGetSymbolAddress((void**)&Kp, g_K);
    cudaGetSymbolAddress((void**)&Vp, g_V);
    cudaGetSymbolAddress((void**)&Cp, g_ctx);

    size_t attn_smem = (size_t)4 * 64 * PITCH * sizeof(float);  // ~69.6 KB
    cudaFuncSetAttribute(attn_kernel, cudaFuncAttributeMaxDynamicSharedMemorySize,
                         (int)attn_smem);

    dim3 ggrid(NN / 128, MM / 128);  // (8, 64)
    gemm_bias_kernel<0><<<ggrid, 256>>>(x, Wq, bq, Qp);
    gemm_bias_kernel<0><<<ggrid, 256>>>(x, Wk, bk, Kp);
    gemm_bias_kernel<0><<<ggrid, 256>>>(x, Wv, bv, Vp);

    attn_kernel<<<dim3(SS / 64, HH, BB), 256, attn_smem>>>(Qp, Kp, Vp, Cp);

    gemm_bias_kernel<1><<<ggrid, 256>>>(Cp, Wo, bo, out);
}

// round 3
// speedup vs baseline: 1.3203x; 1.3203x over previous
#include <cuda_runtime.h>
#include <cuda_bf16.h>
#include <cstdint>
#include <math.h>

#define BB 4
#define SS 2048
#define EE 1024
#define HH 16
#define DKK 64
#define MM (BB*SS)      /* 8192 */
#define NN (HH*DKK)     /* 1024 */
#define KK EE           /* 1024 */

// ---------------------------------------------------------------------------
// Scratch (device globals — no allocation allowed)
// ---------------------------------------------------------------------------
__device__ float g_Q[(size_t)BB*HH*SS*DKK];
__device__ float g_K[(size_t)BB*HH*SS*DKK];
__device__ float g_V[(size_t)BB*HH*SS*DKK];
__device__ float g_ctx[(size_t)MM*NN];

__device__ __nv_bfloat16 g_xhi[(size_t)MM*KK];
__device__ __nv_bfloat16 g_xlo[(size_t)MM*KK];
__device__ __nv_bfloat16 g_chi[(size_t)MM*NN];
__device__ __nv_bfloat16 g_clo[(size_t)MM*NN];
__device__ __nv_bfloat16 g_wthi[(size_t)4*1024*1024];
__device__ __nv_bfloat16 g_wtlo[(size_t)4*1024*1024];

// ---------------------------------------------------------------------------
__device__ __forceinline__ uint32_t smem_u32(const void* p) {
    uint32_t a;
    asm("{ .reg .u64 t; cvta.to.shared.u64 t, %1; cvt.u32.u64 %0, t; }"
        : "=r"(a) : "l"(p));
    return a;
}

// fp32 -> bf16 hi/lo split
__global__ void split_kernel(const float* __restrict__ in,
                             __nv_bfloat16* __restrict__ hi,
                             __nv_bfloat16* __restrict__ lo, int n)
{
    int i = blockIdx.x * blockDim.x + threadIdx.x;
    if (i < n) {
        float v = in[i];
        __nv_bfloat16 h = __float2bfloat16(v);
        hi[i] = h;
        lo[i] = __float2bfloat16(v - __bfloat162float(h));
    }
}

// Transpose W (1024x1024, [K][N]) into K-major ([N][K]) and split hi/lo.
__global__ void transpose_split_kernel(const float* __restrict__ W,
                                       __nv_bfloat16* __restrict__ hi,
                                       __nv_bfloat16* __restrict__ lo)
{
    __shared__ float t[32][33];
    int bx = blockIdx.x * 32, by = blockIdx.y * 32;
    int x = bx + threadIdx.x;
#pragma unroll
    for (int j = 0; j < 32; j += 8)
        t[threadIdx.y + j][threadIdx.x] = W[(size_t)(by + threadIdx.y + j) * 1024 + x];
    __syncthreads();
    int k = by + threadIdx.x;
#pragma unroll
    for (int j = 0; j < 32; j += 8) {
        int n = bx + threadIdx.y + j;
        float v = t[threadIdx.x][threadIdx.y + j];
        __nv_bfloat16 h = __float2bfloat16(v);
        hi[(size_t)n * 1024 + k] = h;
        lo[(size_t)n * 1024 + k] = __float2bfloat16(v - __bfloat162float(h));
    }
}

// ---------------------------------------------------------------------------
// HMMA bf16 split-GEMM: out(M,N) = A(M,K) @ B(K,N) + bias, fp32-equivalent.
//  A: Ahi/Alo bf16 [M][K] row-major.  B: Bhi/Blo bf16 [N][K] (W^T, K-major).
//  3 passes accumulated in fp32 regs: hi*hi, hi*lo, lo*hi.
// MODE 0: split-head out[((b*H+h)*S+s)*DK+d];  MODE 1: row-major out[m*N+n]
// ---------------------------------------------------------------------------
#define NITER 96   /* 3 passes * (1024/32) */

__device__ __forceinline__ uint32_t sw_off(int row, int ch) {
    return (uint32_t)(row * 64 + ((ch ^ ((row >> 1) & 3)) << 4));
}

template <int MODE>
__global__ __launch_bounds__(256) void gemm_mma_kernel(
    const __nv_bfloat16* __restrict__ Ahi, const __nv_bfloat16* __restrict__ Alo,
    const __nv_bfloat16* __restrict__ Bhi, const __nv_bfloat16* __restrict__ Blo,
    const float* __restrict__ bias, float* __restrict__ out)
{
    __shared__ __align__(1024) char smem[3 * 16384];

    const int tid = threadIdx.x;
    const int lane = tid & 31;
    const int wid = tid >> 5;
    const int wm = wid & 3;      // 0..3  (32 rows each)
    const int wn = wid >> 2;     // 0..1  (64 cols each)
    const int m0 = blockIdx.y * 128;
    const int n0 = blockIdx.x * 128;
    const uint32_t sb = smem_u32(smem);

    float c[2][8][4];
#pragma unroll
    for (int i = 0; i < 2; i++)
#pragma unroll
        for (int j = 0; j < 8; j++)
#pragma unroll
            for (int q = 0; q < 4; q++) c[i][j][q] = 0.0f;

    auto issue = [&](int kk) {
        int slot = kk % 3;
        int pass = kk >> 5;
        int kp = (kk & 31) * 32;
        const __nv_bfloat16* As = (pass == 2) ? Alo : Ahi;
        const __nv_bfloat16* Bs = (pass == 1) ? Blo : Bhi;
        uint32_t dA = sb + (uint32_t)slot * 16384u;
        uint32_t dB = dA + 8192u;
#pragma unroll
        for (int i = 0; i < 2; i++) {
            int id = tid + i * 256;
            int row = id >> 2, ch = id & 3;
            uint32_t so = sw_off(row, ch);
            const void* ga = As + (size_t)(m0 + row) * KK + kp + ch * 8;
            asm volatile("cp.async.cg.shared.global [%0], [%1], 16;"
                         :: "r"(dA + so), "l"(ga) : "memory");
            const void* gb = Bs + (size_t)(n0 + row) * KK + kp + ch * 8;
            asm volatile("cp.async.cg.shared.global [%0], [%1], 16;"
                         :: "r"(dB + so), "l"(gb) : "memory");
        }
        asm volatile("cp.async.commit_group;" ::: "memory");
    };

    issue(0);
    issue(1);

    for (int kk = 0; kk < NITER; kk++) {
        if (kk < NITER - 1) asm volatile("cp.async.wait_group 1;" ::: "memory");
        else                asm volatile("cp.async.wait_group 0;" ::: "memory");
        __syncthreads();
        if (kk + 2 < NITER) issue(kk + 2);

        uint32_t aBase = sb + (uint32_t)(kk % 3) * 16384u;
        uint32_t bBase = aBase + 8192u;

#pragma unroll
        for (int ks = 0; ks < 2; ks++) {
            uint32_t a[2][4];
#pragma unroll
            for (int mi = 0; mi < 2; mi++) {
                int row = wm * 32 + mi * 16 + (lane & 15);
                int ch = ks * 2 + (lane >> 4);
                uint32_t addr = aBase + sw_off(row, ch);
                asm volatile("ldmatrix.sync.aligned.m8n8.x4.shared.b16 {%0,%1,%2,%3}, [%4];"
                             : "=r"(a[mi][0]), "=r"(a[mi][1]), "=r"(a[mi][2]), "=r"(a[mi][3])
                             : "r"(addr));
            }
            uint32_t b[4][4];
#pragma unroll
            for (int nj = 0; nj < 4; nj++) {
                int row = wn * 64 + nj * 16 + ((lane >> 4) << 3) + (lane & 7);
                int ch = ks * 2 + ((lane >> 3) & 1);
                uint32_t addr = bBase + sw_off(row, ch);
                asm volatile("ldmatrix.sync.aligned.m8n8.x4.shared.b16 {%0,%1,%2,%3}, [%4];"
                             : "=r"(b[nj][0]), "=r"(b[nj][1]), "=r"(b[nj][2]), "=r"(b[nj][3])
                             : "r"(addr));
            }
#pragma unroll
            for (int mi = 0; mi < 2; mi++)
#pragma unroll
                for (int ni = 0; ni < 8; ni++) {
                    uint32_t b0 = b[ni >> 1][(ni & 1) * 2 + 0];
                    uint32_t b1 = b[ni >> 1][(ni & 1) * 2 + 1];
                    asm volatile(
                        "mma.sync.aligned.m16n8k16.row.col.f32.bf16.bf16.f32 "
                        "{%0,%1,%2,%3}, {%4,%5,%6,%7}, {%8,%9}, {%0,%1,%2,%3};"
                        : "+f"(c[mi][ni][0]), "+f"(c[mi][ni][1]),
                          "+f"(c[mi][ni][2]), "+f"(c[mi][ni][3])
                        : "r"(a[mi][0]), "r"(a[mi][1]), "r"(a[mi][2]), "r"(a[mi][3]),
                          "r"(b0), "r"(b1));
                }
        }
    }

    // epilogue: c frag (mi,ni): rows m0+wm*32+mi*16+lane/4 (+8), cols n0+wn*64+ni*8+(lane%4)*2
#pragma unroll
    for (int mi = 0; mi < 2; mi++) {
#pragma unroll
        for (int ni = 0; ni < 8; ni++) {
            int r0 = m0 + wm * 32 + mi * 16 + (lane >> 2);
            int nc = n0 + wn * 64 + ni * 8 + (lane & 3) * 2;
            float2 bv = *(const float2*)&bias[nc];
            float2 v0 = make_float2(c[mi][ni][0] + bv.x, c[mi][ni][1] + bv.y);
            float2 v1 = make_float2(c[mi][ni][2] + bv.x, c[mi][ni][3] + bv.y);
#pragma unroll
            for (int rr = 0; rr < 2; rr++) {
                int m = r0 + rr * 8;
                float2 v = rr ? v1 : v0;
                if (MODE == 0) {
                    int bb = m >> 11, s = m & (SS - 1);
                    int h = nc >> 6, d = nc & 63;
                    *(float2*)&out[(((size_t)bb * HH + h) * SS + s) * DKK + d] = v;
                } else {
                    *(float2*)&out[(size_t)m * NN + nc] = v;
                }
            }
        }
    }
}

// ---------------------------------------------------------------------------
// Flash attention (SIMT, unchanged)
// ---------------------------------------------------------------------------
#define PITCH 68

__global__ __launch_bounds__(256) void attn_kernel(
    const float* __restrict__ Q, const float* __restrict__ K,
    const float* __restrict__ V, float* __restrict__ O)
{
    extern __shared__ float sm[];
    float (*Qs)[PITCH] = (float(*)[PITCH])(sm);
    float (*Ks)[PITCH] = (float(*)[PITCH])(sm + 64 * PITCH);
    float (*Vs)[PITCH] = (float(*)[PITCH])(sm + 2 * 64 * PITCH);
    float (*Ps)[PITCH] = (float(*)[PITCH])(sm + 3 * 64 * PITCH);

    const int tid = threadIdx.x;
    const int b = blockIdx.z, h = blockIdx.y;
    const int q0 = blockIdx.x * 64;
    const size_t base = ((size_t)b * HH + h) * SS * DKK;

    const float scale = 0.125f;

    for (int i = tid; i < 64 * 16; i += 256) {
        int r = i >> 4, c = (i & 15) * 4;
        float4 v = *(const float4*)(Q + base + (size_t)(q0 + r) * DKK + c);
        v.x *= scale; v.y *= scale; v.z *= scale; v.w *= scale;
        *(float4*)&Qs[r][c] = v;
    }

    const int tm0 = (tid >> 4) * 4;
    const int tn0 = (tid & 15) * 4;

    float o[4][4];
#pragma unroll
    for (int i = 0; i < 4; i++)
#pragma unroll
        for (int j = 0; j < 4; j++) o[i][j] = 0.0f;
    float mrow[4] = {-INFINITY, -INFINITY, -INFINITY, -INFINITY};
    float lrow[4] = {0.f, 0.f, 0.f, 0.f};

    for (int kt = 0; kt < SS; kt += 64) {
        __syncthreads();
        for (int i = tid; i < 64 * 16; i += 256) {
            int r = i >> 4, c = (i & 15) * 4;
            *(float4*)&Ks[r][c] = *(const float4*)(K + base + (size_t)(kt + r) * DKK + c);
            *(float4*)&Vs[r][c] = *(const float4*)(V + base + (size_t)(kt + r) * DKK + c);
        }
        __syncthreads();

        float s[4][4];
#pragma unroll
        for (int i = 0; i < 4; i++)
#pragma unroll
            for (int j = 0; j < 4; j++) s[i][j] = 0.0f;

#pragma unroll 4
        for (int d = 0; d < 64; d += 4) {
            float4 a[4], bb[4];
#pragma unroll
            for (int i = 0; i < 4; i++) a[i] = *(float4*)&Qs[tm0 + i][d];
#pragma unroll
            for (int j = 0; j < 4; j++) bb[j] = *(float4*)&Ks[tn0 + j][d];
#pragma unroll
            for (int i = 0; i < 4; i++)
#pragma unroll
                for (int j = 0; j < 4; j++) {
                    s[i][j] = fmaf(a[i].x, bb[j].x, s[i][j]);
                    s[i][j] = fmaf(a[i].y, bb[j].y, s[i][j]);
                    s[i][j] = fmaf(a[i].z, bb[j].z, s[i][j]);
                    s[i][j] = fmaf(a[i].w, bb[j].w, s[i][j]);
                }
        }

#pragma unroll
        for (int i = 0; i < 4; i++) {
            float mx = fmaxf(fmaxf(s[i][0], s[i][1]), fmaxf(s[i][2], s[i][3]));
#pragma unroll
            for (int off = 1; off < 16; off <<= 1)
                mx = fmaxf(mx, __shfl_xor_sync(0xffffffffu, mx, off));
            float mnew = fmaxf(mrow[i], mx);
            float alpha = __expf(mrow[i] - mnew);
            float ps = 0.f;
#pragma unroll
            for (int j = 0; j < 4; j++) {
                s[i][j] = __expf(s[i][j] - mnew);
                ps += s[i][j];
            }
#pragma unroll
            for (int off = 1; off < 16; off <<= 1)
                ps += __shfl_xor_sync(0xffffffffu, ps, off);
            lrow[i] = lrow[i] * alpha + ps;
            mrow[i] = mnew;
#pragma unroll
            for (int d = 0; d < 4; d++) o[i][d] *= alpha;
        }

#pragma unroll
        for (int i = 0; i < 4; i++) {
            float4 pv = make_float4(s[i][0], s[i][1], s[i][2], s[i][3]);
            *(float4*)&Ps[tm0 + i][tn0] = pv;
        }
        __syncthreads();

#pragma unroll 4
        for (int j = 0; j < 64; j += 4) {
            float4 p[4];
#pragma unroll
            for (int i = 0; i < 4; i++) p[i] = *(float4*)&Ps[tm0 + i][j];
            float4 v0 = *(float4*)&Vs[j + 0][tn0];
            float4 v1 = *(float4*)&Vs[j + 1][tn0];
            float4 v2 = *(float4*)&Vs[j + 2][tn0];
            float4 v3 = *(float4*)&Vs[j + 3][tn0];
#pragma unroll
            for (int i = 0; i < 4; i++) {
                o[i][0] = fmaf(p[i].x, v0.x, o[i][0]);
                o[i][1] = fmaf(p[i].x, v0.y, o[i][1]);
                o[i][2] = fmaf(p[i].x, v0.z, o[i][2]);
                o[i][3] = fmaf(p[i].x, v0.w, o[i][3]);
                o[i][0] = fmaf(p[i].y, v1.x, o[i][0]);
                o[i][1] = fmaf(p[i].y, v1.y, o[i][1]);
                o[i][2] = fmaf(p[i].y, v1.z, o[i][2]);
                o[i][3] = fmaf(p[i].y, v1.w, o[i][3]);
                o[i][0] = fmaf(p[i].z, v2.x, o[i][0]);
                o[i][1] = fmaf(p[i].z, v2.y, o[i][1]);
                o[i][2] = fmaf(p[i].z, v2.z, o[i][2]);
                o[i][3] = fmaf(p[i].z, v2.w, o[i][3]);
                o[i][0] = fmaf(p[i].w, v3.x, o[i][0]);
                o[i][1] = fmaf(p[i].w, v3.y, o[i][1]);
                o[i][2] = fmaf(p[i].w, v3.z, o[i][2]);
                o[i][3] = fmaf(p[i].w, v3.w, o[i][3]);
            }
        }
    }

#pragma unroll
    for (int i = 0; i < 4; i++) {
        float inv = 1.0f / lrow[i];
        int s_idx = q0 + tm0 + i;
        float4 v = make_float4(o[i][0] * inv, o[i][1] * inv, o[i][2] * inv, o[i][3] * inv);
        *(float4*)&O[(((size_t)b * SS + s_idx) * HH + h) * DKK + tn0] = v;
    }
}

// ---------------------------------------------------------------------------
extern "C" void kernel_launch(void* const* d_in, const int* in_sizes, int n_in,
                              void* d_out, int out_size)
{
    const float* x  = (const float*)d_in[0];
    const float* Wq = (const float*)d_in[1];
    const float* bq = (const float*)d_in[2];
    const float* Wk = (const float*)d_in[3];
    const float* bk = (const float*)d_in[4];
    const float* Wv = (const float*)d_in[5];
    const float* bv = (const float*)d_in[6];
    const float* Wo = (const float*)d_in[7];
    const float* bo = (const float*)d_in[8];
    float* out = (float*)d_out;

    float *Qp, *Kp, *Vp, *Cp;
    cudaGetSymbolAddress((void**)&Qp, g_Q);
    cudaGetSymbolAddress((void**)&Kp, g_K);
    cudaGetSymbolAddress((void**)&Vp, g_V);
    cudaGetSymbolAddress((void**)&Cp, g_ctx);
    __nv_bfloat16 *xhi, *xlo, *chi, *clo, *wthi, *wtlo;
    cudaGetSymbolAddress((void**)&xhi, g_xhi);
    cudaGetSymbolAddress((void**)&xlo, g_xlo);
    cudaGetSymbolAddress((void**)&chi, g_chi);
    cudaGetSymbolAddress((void**)&clo, g_clo);
    cudaGetSymbolAddress((void**)&wthi, g_wthi);
    cudaGetSymbolAddress((void**)&wtlo, g_wtlo);

    size_t attn_smem = (size_t)4 * 64 * PITCH * sizeof(float);
    cudaFuncSetAttribute(attn_kernel, cudaFuncAttributeMaxDynamicSharedMemorySize, (int)attn_smem);

    const size_t WSZ = (size_t)1024 * 1024;

    // 1. split x into bf16 hi/lo
    split_kernel<<<(MM * KK + 255) / 256, 256>>>(x, xhi, xlo, MM * KK);

    // 2. transpose + split the four weight matrices
    dim3 tgrid(32, 32), tblk(32, 8);
    transpose_split_kernel<<<tgrid, tblk>>>(Wq, wthi + 0 * WSZ, wtlo + 0 * WSZ);
    transpose_split_kernel<<<tgrid, tblk>>>(Wk, wthi + 1 * WSZ, wtlo + 1 * WSZ);
    transpose_split_kernel<<<tgrid, tblk>>>(Wv, wthi + 2 * WSZ, wtlo + 2 * WSZ);
    transpose_split_kernel<<<tgrid, tblk>>>(Wo, wthi + 3 * WSZ, wtlo + 3 * WSZ);

    // 3. projections (HMMA, split-head output)
    dim3 ggrid(NN / 128, MM / 128);  // (8, 64)
    gemm_mma_kernel<0><<<ggrid, 256>>>(xhi, xlo, wthi + 0 * WSZ, wtlo + 0 * WSZ, bq, Qp);
    gemm_mma_kernel<0><<<ggrid, 256>>>(xhi, xlo, wthi + 1 * WSZ, wtlo + 1 * WSZ, bk, Kp);
    gemm_mma_kernel<0><<<ggrid, 256>>>(xhi, xlo, wthi + 2 * WSZ, wtlo + 2 * WSZ, bv, Vp);

    // 4. attention (SIMT, unchanged)
    attn_kernel<<<dim3(SS / 64, HH, BB), 256, attn_smem>>>(Qp, Kp, Vp, Cp);

    // 5. output projection
    split_kernel<<<(MM * NN + 255) / 256, 256>>>(Cp, chi, clo, MM * NN);
    gemm_mma_kernel<1><<<ggrid, 256>>>(chi, clo, wthi + 3 * WSZ, wtlo + 3 * WSZ, bo, out);
}

// round 4
// speedup vs baseline: 3.7370x; 2.8304x over previous
#include <cuda_runtime.h>
#include <cuda_bf16.h>
#include <cstdint>
#include <math.h>

#define BB 4
#define SS 2048
#define EE 1024
#define HH 16
#define DKK 64
#define MM (BB*SS)      /* 8192 */
#define NN (HH*DKK)     /* 1024 */
#define KK EE           /* 1024 */

// ---------------------------------------------------------------------------
// Scratch (device globals — no allocation allowed)
// ---------------------------------------------------------------------------
__device__ __nv_bfloat16 g_qhi[(size_t)MM*NN];
__device__ __nv_bfloat16 g_qlo[(size_t)MM*NN];
__device__ __nv_bfloat16 g_khi[(size_t)MM*NN];
__device__ __nv_bfloat16 g_klo[(size_t)MM*NN];
__device__ __nv_bfloat16 g_vhi[(size_t)MM*NN];
__device__ __nv_bfloat16 g_vlo[(size_t)MM*NN];
__device__ __nv_bfloat16 g_xhi[(size_t)MM*KK];
__device__ __nv_bfloat16 g_xlo[(size_t)MM*KK];
__device__ __nv_bfloat16 g_chi[(size_t)MM*NN];
__device__ __nv_bfloat16 g_clo[(size_t)MM*NN];
__device__ __nv_bfloat16 g_wthi[(size_t)4*1024*1024];
__device__ __nv_bfloat16 g_wtlo[(size_t)4*1024*1024];

// ---------------------------------------------------------------------------
__device__ __forceinline__ uint32_t smem_u32(const void* p) {
    uint32_t a;
    asm("{ .reg .u64 t; cvta.to.shared.u64 t, %1; cvt.u32.u64 %0, t; }"
        : "=r"(a) : "l"(p));
    return a;
}

#define MMA16816(C, A, B0, B1) \
    asm volatile("mma.sync.aligned.m16n8k16.row.col.f32.bf16.bf16.f32 " \
                 "{%0,%1,%2,%3}, {%4,%5,%6,%7}, {%8,%9}, {%0,%1,%2,%3};" \
                 : "+f"((C)[0]), "+f"((C)[1]), "+f"((C)[2]), "+f"((C)[3]) \
                 : "r"((A)[0]), "r"((A)[1]), "r"((A)[2]), "r"((A)[3]), \
                   "r"(B0), "r"(B1))

#define LDSM4(R, addr) \
    asm volatile("ldmatrix.sync.aligned.m8n8.x4.shared.b16 {%0,%1,%2,%3}, [%4];" \
                 : "=r"((R)[0]), "=r"((R)[1]), "=r"((R)[2]), "=r"((R)[3]) : "r"(addr))

#define LDSM4T(R, addr) \
    asm volatile("ldmatrix.sync.aligned.m8n8.x4.trans.shared.b16 {%0,%1,%2,%3}, [%4];" \
                 : "=r"((R)[0]), "=r"((R)[1]), "=r"((R)[2]), "=r"((R)[3]) : "r"(addr))

#define CPASYNC16(dst, src) \
    asm volatile("cp.async.cg.shared.global [%0], [%1], 16;" :: "r"(dst), "l"(src) : "memory")

__device__ __forceinline__ uint32_t pack_split(float x, float y, uint32_t& lo) {
    __nv_bfloat162 h2 = __floats2bfloat162_rn(x, y);
    float rx = x - __low2float(h2);
    float ry = y - __high2float(h2);
    __nv_bfloat162 l2 = __floats2bfloat162_rn(rx, ry);
    lo = *(uint32_t*)&l2;
    return *(uint32_t*)&h2;
}

// fp32 -> bf16 hi/lo split
__global__ void split_kernel(const float* __restrict__ in,
                             __nv_bfloat16* __restrict__ hi,
                             __nv_bfloat16* __restrict__ lo, int n)
{
    int i = blockIdx.x * blockDim.x + threadIdx.x;
    if (i < n) {
        float v = in[i];
        __nv_bfloat16 h = __float2bfloat16(v);
        hi[i] = h;
        lo[i] = __float2bfloat16(v - __bfloat162float(h));
    }
}

// Transpose W (1024x1024, [K][N]) into K-major ([N][K]) and split hi/lo.
__global__ void transpose_split_kernel(const float* __restrict__ W,
                                       __nv_bfloat16* __restrict__ hi,
                                       __nv_bfloat16* __restrict__ lo)
{
    __shared__ float t[32][33];
    int bx = blockIdx.x * 32, by = blockIdx.y * 32;
    int x = bx + threadIdx.x;
#pragma unroll
    for (int j = 0; j < 32; j += 8)
        t[threadIdx.y + j][threadIdx.x] = W[(size_t)(by + threadIdx.y + j) * 1024 + x];
    __syncthreads();
    int k = by + threadIdx.x;
#pragma unroll
    for (int j = 0; j < 32; j += 8) {
        int n = bx + threadIdx.y + j;
        float v = t[threadIdx.x][threadIdx.y + j];
        __nv_bfloat16 h = __float2bfloat16(v);
        hi[(size_t)n * 1024 + k] = h;
        lo[(size_t)n * 1024 + k] = __float2bfloat16(v - __bfloat162float(h));
    }
}

// ---------------------------------------------------------------------------
// HMMA bf16 split-GEMM (3 passes, fp32-equivalent).
// MODE 0: write bf16 hi/lo, split-head layout, scaled.
// MODE 1: write fp32 row-major out.
// ---------------------------------------------------------------------------
#define NITER 96

__device__ __forceinline__ uint32_t sw_off64(int row, int ch) {
    return (uint32_t)(row * 64 + ((ch ^ ((row >> 1) & 3)) << 4));
}

template <int MODE>
__global__ __launch_bounds__(256) void gemm_mma_kernel(
    const __nv_bfloat16* __restrict__ Ahi, const __nv_bfloat16* __restrict__ Alo,
    const __nv_bfloat16* __restrict__ Bhi, const __nv_bfloat16* __restrict__ Blo,
    const float* __restrict__ bias, float* __restrict__ out,
    __nv_bfloat16* __restrict__ ohi, __nv_bfloat16* __restrict__ olo, float scale)
{
    __shared__ __align__(1024) char smem[3 * 16384];

    const int tid = threadIdx.x;
    const int lane = tid & 31;
    const int wid = tid >> 5;
    const int wm = wid & 3;
    const int wn = wid >> 2;
    const int m0 = blockIdx.y * 128;
    const int n0 = blockIdx.x * 128;
    const uint32_t sb = smem_u32(smem);

    float c[2][8][4];
#pragma unroll
    for (int i = 0; i < 2; i++)
#pragma unroll
        for (int j = 0; j < 8; j++)
#pragma unroll
            for (int q = 0; q < 4; q++) c[i][j][q] = 0.0f;

    auto issue = [&](int kk) {
        int slot = kk % 3;
        int pass = kk >> 5;
        int kp = (kk & 31) * 32;
        const __nv_bfloat16* As = (pass == 2) ? Alo : Ahi;
        const __nv_bfloat16* Bs = (pass == 1) ? Blo : Bhi;
        uint32_t dA = sb + (uint32_t)slot * 16384u;
        uint32_t dB = dA + 8192u;
#pragma unroll
        for (int i = 0; i < 2; i++) {
            int id = tid + i * 256;
            int row = id >> 2, ch = id & 3;
            uint32_t so = sw_off64(row, ch);
            CPASYNC16(dA + so, As + (size_t)(m0 + row) * KK + kp + ch * 8);
            CPASYNC16(dB + so, Bs + (size_t)(n0 + row) * KK + kp + ch * 8);
        }
        asm volatile("cp.async.commit_group;" ::: "memory");
    };

    issue(0);
    issue(1);

    for (int kk = 0; kk < NITER; kk++) {
        if (kk < NITER - 1) asm volatile("cp.async.wait_group 1;" ::: "memory");
        else                asm volatile("cp.async.wait_group 0;" ::: "memory");
        __syncthreads();
        if (kk + 2 < NITER) issue(kk + 2);

        uint32_t aBase = sb + (uint32_t)(kk % 3) * 16384u;
        uint32_t bBase = aBase + 8192u;

#pragma unroll
        for (int ks = 0; ks < 2; ks++) {
            uint32_t a[2][4];
#pragma unroll
            for (int mi = 0; mi < 2; mi++) {
                int row = wm * 32 + mi * 16 + (lane & 15);
                int ch = ks * 2 + (lane >> 4);
                LDSM4(a[mi], aBase + sw_off64(row, ch));
            }
            uint32_t b[4][4];
#pragma unroll
            for (int nj = 0; nj < 4; nj++) {
                int row = wn * 64 + nj * 16 + ((lane >> 4) << 3) + (lane & 7);
                int ch = ks * 2 + ((lane >> 3) & 1);
                LDSM4(b[nj], bBase + sw_off64(row, ch));
            }
#pragma unroll
            for (int mi = 0; mi < 2; mi++)
#pragma unroll
                for (int ni = 0; ni < 8; ni++) {
                    MMA16816(c[mi][ni], a[mi],
                             b[ni >> 1][(ni & 1) * 2 + 0], b[ni >> 1][(ni & 1) * 2 + 1]);
                }
        }
    }

#pragma unroll
    for (int mi = 0; mi < 2; mi++) {
#pragma unroll
        for (int ni = 0; ni < 8; ni++) {
            int r0 = m0 + wm * 32 + mi * 16 + (lane >> 2);
            int nc = n0 + wn * 64 + ni * 8 + (lane & 3) * 2;
            float2 bv = *(const float2*)&bias[nc];
#pragma unroll
            for (int rr = 0; rr < 2; rr++) {
                int m = r0 + rr * 8;
                float vx = (c[mi][ni][rr * 2 + 0] + bv.x) * scale;
                float vy = (c[mi][ni][rr * 2 + 1] + bv.y) * scale;
                if (MODE == 0) {
                    int bb = m >> 11, s = m & (SS - 1);
                    int h = nc >> 6, d = nc & 63;
                    size_t idx = (((size_t)bb * HH + h) * SS + s) * DKK + d;
                    uint32_t lo, hi = pack_split(vx, vy, lo);
                    *(uint32_t*)&ohi[idx] = hi;
                    *(uint32_t*)&olo[idx] = lo;
                } else {
                    *(float2*)&out[(size_t)m * NN + nc] = make_float2(vx, vy);
                }
            }
        }
    }
}

// ---------------------------------------------------------------------------
// HMMA flash attention: 128 q-rows/CTA, 128-key tiles, hi/lo split QK and PV.
// Writes ctx directly as bf16 hi/lo in [b][s][h*64+d] layout.
// ---------------------------------------------------------------------------
__device__ __forceinline__ uint32_t sw_off128(int row, int ch) {
    return (uint32_t)(row * 128 + ((ch ^ (row & 7)) << 4));
}

#define ATTN_SMEM 163840
#define OFF_QHI 0
#define OFF_QLO 16384
#define OFF_STG 32768   /* stage s at OFF_STG + s*65536; khi,klo,vhi,vlo each 16384 */

__global__ __launch_bounds__(256, 1) void attn_mma_kernel(
    const __nv_bfloat16* __restrict__ Qhi, const __nv_bfloat16* __restrict__ Qlo,
    const __nv_bfloat16* __restrict__ Khi, const __nv_bfloat16* __restrict__ Klo,
    const __nv_bfloat16* __restrict__ Vhi, const __nv_bfloat16* __restrict__ Vlo,
    __nv_bfloat16* __restrict__ Chi, __nv_bfloat16* __restrict__ Clo)
{
    extern __shared__ __align__(1024) char dsm[];
    const uint32_t sb = smem_u32(dsm);

    const int tid = threadIdx.x;
    const int lane = tid & 31;
    const int wm = tid >> 5;           // warp 0..7 -> q rows wm*16
    const int b = blockIdx.z, h = blockIdx.y;
    const int q0 = blockIdx.x * 128;
    const size_t base = ((size_t)b * HH + h) * SS * DKK;

    // ---- issue Q loads (group 0)
    {
        uint32_t dh = sb + OFF_QHI, dl = sb + OFF_QLO;
#pragma unroll
        for (int i = 0; i < 4; i++) {
            int id = tid + i * 256;
            int row = id >> 3, ch = id & 7;
            uint32_t so = sw_off128(row, ch);
            CPASYNC16(dh + so, Qhi + base + (size_t)(q0 + row) * DKK + ch * 8);
            CPASYNC16(dl + so, Qlo + base + (size_t)(q0 + row) * DKK + ch * 8);
        }
        asm volatile("cp.async.commit_group;" ::: "memory");
    }

    auto issue_kv = [&](int t, int stg) {
        uint32_t st = sb + OFF_STG + (uint32_t)stg * 65536u;
        const __nv_bfloat16* bufs[4] = {Khi, Klo, Vhi, Vlo};
#pragma unroll
        for (int bu = 0; bu < 4; bu++) {
            uint32_t dst = st + (uint32_t)bu * 16384u;
            const __nv_bfloat16* src = bufs[bu];
#pragma unroll
            for (int i = 0; i < 4; i++) {
                int id = tid + i * 256;
                int row = id >> 3, ch = id & 7;
                CPASYNC16(dst + sw_off128(row, ch),
                          src + base + (size_t)(t * 128 + row) * DKK + ch * 8);
            }
        }
        asm volatile("cp.async.commit_group;" ::: "memory");
    };

    issue_kv(0, 0);
    issue_kv(1, 1);

    // ---- Q fragments (wait only for group 0; keep 2 pending)
    asm volatile("cp.async.wait_group 2;" ::: "memory");
    __syncthreads();

    uint32_t qh[4][4], ql[4][4];
#pragma unroll
    for (int ks = 0; ks < 4; ks++) {
        int row = wm * 16 + (lane & 15);
        int ch = ks * 2 + (lane >> 4);
        LDSM4(qh[ks], sb + OFF_QHI + sw_off128(row, ch));
        LDSM4(ql[ks], sb + OFF_QLO + sw_off128(row, ch));
    }

    float o[8][4];
#pragma unroll
    for (int i = 0; i < 8; i++)
#pragma unroll
        for (int j = 0; j < 4; j++) o[i][j] = 0.0f;
    float m0 = -1e30f, m1 = -1e30f, l0 = 0.0f, l1 = 0.0f;

    for (int t = 0; t < 16; t++) {
        if (t < 15) asm volatile("cp.async.wait_group 1;" ::: "memory");
        else        asm volatile("cp.async.wait_group 0;" ::: "memory");
        __syncthreads();

        uint32_t st = sb + OFF_STG + (uint32_t)(t & 1) * 65536u;
        uint32_t kh = st, kl = st + 16384u, vh = st + 32768u, vl = st + 49152u;

        // ---- S = Qhi*Khi + Qlo*Khi + Qhi*Klo
        float s[16][4];
#pragma unroll
        for (int i = 0; i < 16; i++)
#pragma unroll
            for (int j = 0; j < 4; j++) s[i][j] = 0.0f;

#pragma unroll
        for (int ks = 0; ks < 4; ks++) {
#pragma unroll
            for (int nj = 0; nj < 8; nj++) {
                int row = nj * 16 + ((lane >> 4) << 3) + (lane & 7);
                int ch = ks * 2 + ((lane >> 3) & 1);
                uint32_t bh[4], bl[4];
                LDSM4(bh, kh + sw_off128(row, ch));
                LDSM4(bl, kl + sw_off128(row, ch));
#pragma unroll
                for (int half = 0; half < 2; half++) {
                    int ni = nj * 2 + half;
                    uint32_t b0 = bh[half * 2], b1 = bh[half * 2 + 1];
                    MMA16816(s[ni], qh[ks], b0, b1);
                    MMA16816(s[ni], ql[ks], b0, b1);
                    MMA16816(s[ni], qh[ks], bl[half * 2], bl[half * 2 + 1]);
                }
            }
        }

        // ---- online softmax (rows lane/4 and lane/4+8, warp-private)
        float mt0 = -1e30f, mt1 = -1e30f;
#pragma unroll
        for (int ni = 0; ni < 16; ni++) {
            mt0 = fmaxf(mt0, fmaxf(s[ni][0], s[ni][1]));
            mt1 = fmaxf(mt1, fmaxf(s[ni][2], s[ni][3]));
        }
        mt0 = fmaxf(mt0, __shfl_xor_sync(0xffffffffu, mt0, 1));
        mt0 = fmaxf(mt0, __shfl_xor_sync(0xffffffffu, mt0, 2));
        mt1 = fmaxf(mt1, __shfl_xor_sync(0xffffffffu, mt1, 1));
        mt1 = fmaxf(mt1, __shfl_xor_sync(0xffffffffu, mt1, 2));
        float mn0 = fmaxf(m0, mt0), mn1 = fmaxf(m1, mt1);
        float a0 = __expf(m0 - mn0), a1 = __expf(m1 - mn1);
        float ps0 = 0.0f, ps1 = 0.0f;
#pragma unroll
        for (int ni = 0; ni < 16; ni++) {
            s[ni][0] = __expf(s[ni][0] - mn0);
            s[ni][1] = __expf(s[ni][1] - mn0);
            s[ni][2] = __expf(s[ni][2] - mn1);
            s[ni][3] = __expf(s[ni][3] - mn1);
            ps0 += s[ni][0] + s[ni][1];
            ps1 += s[ni][2] + s[ni][3];
        }
        ps0 += __shfl_xor_sync(0xffffffffu, ps0, 1);
        ps0 += __shfl_xor_sync(0xffffffffu, ps0, 2);
        ps1 += __shfl_xor_sync(0xffffffffu, ps1, 1);
        ps1 += __shfl_xor_sync(0xffffffffu, ps1, 2);
        l0 = l0 * a0 + ps0; l1 = l1 * a1 + ps1;
        m0 = mn0; m1 = mn1;
#pragma unroll
        for (int ni = 0; ni < 8; ni++) {
            o[ni][0] *= a0; o[ni][1] *= a0;
            o[ni][2] *= a1; o[ni][3] *= a1;
        }

        // ---- O += P*V  (phi*vhi + plo*vhi + phi*vlo)
#pragma unroll
        for (int kb = 0; kb < 8; kb++) {
            uint32_t ph[4], pl[4];
            ph[0] = pack_split(s[2*kb][0],   s[2*kb][1],   pl[0]);
            ph[1] = pack_split(s[2*kb][2],   s[2*kb][3],   pl[1]);
            ph[2] = pack_split(s[2*kb+1][0], s[2*kb+1][1], pl[2]);
            ph[3] = pack_split(s[2*kb+1][2], s[2*kb+1][3], pl[3]);
#pragma unroll
            for (int dj = 0; dj < 4; dj++) {
                int qm = lane >> 3;
                int row = kb * 16 + (qm & 1) * 8 + (lane & 7);
                int ch = dj * 2 + (qm >> 1);
                uint32_t vr[4], vlr[4];
                LDSM4T(vr,  vh + sw_off128(row, ch));
                LDSM4T(vlr, vl + sw_off128(row, ch));
#pragma unroll
                for (int half = 0; half < 2; half++) {
                    int ni = dj * 2 + half;
                    uint32_t b0 = vr[half * 2], b1 = vr[half * 2 + 1];
                    MMA16816(o[ni], ph, b0, b1);
                    MMA16816(o[ni], pl, b0, b1);
                    MMA16816(o[ni], ph, vlr[half * 2], vlr[half * 2 + 1]);
                }
            }
        }

        __syncthreads();
        if (t + 2 < 16) issue_kv(t + 2, t & 1);
    }

    // ---- epilogue: normalize, split hi/lo, store ctx [b][s][h*64+d]
    float inv0 = 1.0f / l0, inv1 = 1.0f / l1;
    int srow0 = q0 + wm * 16 + (lane >> 2);
#pragma unroll
    for (int ni = 0; ni < 8; ni++) {
        int d = ni * 8 + (lane & 3) * 2;
        size_t i0 = ((size_t)b * SS + srow0) * NN + h * DKK + d;
        size_t i1 = ((size_t)b * SS + srow0 + 8) * NN + h * DKK + d;
        uint32_t lo, hi;
        hi = pack_split(o[ni][0] * inv0, o[ni][1] * inv0, lo);
        *(uint32_t*)&Chi[i0] = hi;  *(uint32_t*)&Clo[i0] = lo;
        hi = pack_split(o[ni][2] * inv1, o[ni][3] * inv1, lo);
        *(uint32_t*)&Chi[i1] = hi;  *(uint32_t*)&Clo[i1] = lo;
    }
}

// ---------------------------------------------------------------------------
extern "C" void kernel_launch(void* const* d_in, const int* in_sizes, int n_in,
                              void* d_out, int out_size)
{
    const float* x  = (const float*)d_in[0];
    const float* Wq = (const float*)d_in[1];
    const float* bq = (const float*)d_in[2];
    const float* Wk = (const float*)d_in[3];
    const float* bk = (const float*)d_in[4];
    const float* Wv = (const float*)d_in[5];
    const float* bv = (const float*)d_in[6];
    const float* Wo = (const float*)d_in[7];
    const float* bo = (const float*)d_in[8];
    float* out = (float*)d_out;

    __nv_bfloat16 *qhi, *qlo, *khi, *klo, *vhi, *vlo, *xhi, *xlo, *chi, *clo, *wthi, *wtlo;
    cudaGetSymbolAddress((void**)&qhi, g_qhi);
    cudaGetSymbolAddress((void**)&qlo, g_qlo);
    cudaGetSymbolAddress((void**)&khi, g_khi);
    cudaGetSymbolAddress((void**)&klo, g_klo);
    cudaGetSymbolAddress((void**)&vhi, g_vhi);
    cudaGetSymbolAddress((void**)&vlo, g_vlo);
    cudaGetSymbolAddress((void**)&xhi, g_xhi);
    cudaGetSymbolAddress((void**)&xlo, g_xlo);
    cudaGetSymbolAddress((void**)&chi, g_chi);
    cudaGetSymbolAddress((void**)&clo, g_clo);
    cudaGetSymbolAddress((void**)&wthi, g_wthi);
    cudaGetSymbolAddress((void**)&wtlo, g_wtlo);

    cudaFuncSetAttribute(attn_mma_kernel, cudaFuncAttributeMaxDynamicSharedMemorySize, ATTN_SMEM);

    const size_t WSZ = (size_t)1024 * 1024;

    split_kernel<<<(MM * KK + 255) / 256, 256>>>(x, xhi, xlo, MM * KK);

    dim3 tgrid(32, 32), tblk(32, 8);
    transpose_split_kernel<<<tgrid, tblk>>>(Wq, wthi + 0 * WSZ, wtlo + 0 * WSZ);
    transpose_split_kernel<<<tgrid, tblk>>>(Wk, wthi + 1 * WSZ, wtlo + 1 * WSZ);
    transpose_split_kernel<<<tgrid, tblk>>>(Wv, wthi + 2 * WSZ, wtlo + 2 * WSZ);
    transpose_split_kernel<<<tgrid, tblk>>>(Wo, wthi + 3 * WSZ, wtlo + 3 * WSZ);

    dim3 ggrid(NN / 128, MM / 128);
    gemm_mma_kernel<0><<<ggrid, 256>>>(xhi, xlo, wthi + 0 * WSZ, wtlo + 0 * WSZ, bq,
                                       nullptr, qhi, qlo, 0.125f);
    gemm_mma_kernel<0><<<ggrid, 256>>>(xhi, xlo, wthi + 1 * WSZ, wtlo + 1 * WSZ, bk,
                                       nullptr, khi, klo, 1.0f);
    gemm_mma_kernel<0><<<ggrid, 256>>>(xhi, xlo, wthi + 2 * WSZ, wtlo + 2 * WSZ, bv,
                                       nullptr, vhi, vlo, 1.0f);

    attn_mma_kernel<<<dim3(SS / 128, HH, BB), 256, ATTN_SMEM>>>(
        qhi, qlo, khi, klo, vhi, vlo, chi, clo);

    gemm_mma_kernel<1><<<ggrid, 256>>>(chi, clo, wthi + 3 * WSZ, wtlo + 3 * WSZ, bo,
                                       out, nullptr, nullptr, 1.0f);
}

// round 5
// speedup vs baseline: 4.5315x; 1.2126x over previous
#include <cuda_runtime.h>
#include <cuda_bf16.h>
#include <cstdint>
#include <math.h>

#define BB 4
#define SS 2048
#define EE 1024
#define HH 16
#define DKK 64
#define MM (BB*SS)      /* 8192 */
#define NN (HH*DKK)     /* 1024 */
#define KK EE           /* 1024 */

// ---------------------------------------------------------------------------
// Scratch (device globals — no allocation allowed)
// ---------------------------------------------------------------------------
__device__ __nv_bfloat16 g_qhi[(size_t)MM*NN];
__device__ __nv_bfloat16 g_qlo[(size_t)MM*NN];
__device__ __nv_bfloat16 g_khi[(size_t)MM*NN];
__device__ __nv_bfloat16 g_klo[(size_t)MM*NN];
__device__ __nv_bfloat16 g_vhi[(size_t)MM*NN];
__device__ __nv_bfloat16 g_vlo[(size_t)MM*NN];
__device__ __nv_bfloat16 g_xhi[(size_t)MM*KK];
__device__ __nv_bfloat16 g_xlo[(size_t)MM*KK];
__device__ __nv_bfloat16 g_chi[(size_t)MM*NN];
__device__ __nv_bfloat16 g_clo[(size_t)MM*NN];
__device__ __nv_bfloat16 g_wthi[(size_t)4*1024*1024];
__device__ __nv_bfloat16 g_wtlo[(size_t)4*1024*1024];

// ---------------------------------------------------------------------------
__device__ __forceinline__ uint32_t smem_u32(const void* p) {
    uint32_t a;
    asm("{ .reg .u64 t; cvta.to.shared.u64 t, %1; cvt.u32.u64 %0, t; }"
        : "=r"(a) : "l"(p));
    return a;
}

#define MMA16816(C, A, B0, B1) \
    asm volatile("mma.sync.aligned.m16n8k16.row.col.f32.bf16.bf16.f32 " \
                 "{%0,%1,%2,%3}, {%4,%5,%6,%7}, {%8,%9}, {%0,%1,%2,%3};" \
                 : "+f"((C)[0]), "+f"((C)[1]), "+f"((C)[2]), "+f"((C)[3]) \
                 : "r"((A)[0]), "r"((A)[1]), "r"((A)[2]), "r"((A)[3]), \
                   "r"(B0), "r"(B1))

#define LDSM4(R, addr) \
    asm volatile("ldmatrix.sync.aligned.m8n8.x4.shared.b16 {%0,%1,%2,%3}, [%4];" \
                 : "=r"((R)[0]), "=r"((R)[1]), "=r"((R)[2]), "=r"((R)[3]) : "r"(addr))

#define LDSM4T(R, addr) \
    asm volatile("ldmatrix.sync.aligned.m8n8.x4.trans.shared.b16 {%0,%1,%2,%3}, [%4];" \
                 : "=r"((R)[0]), "=r"((R)[1]), "=r"((R)[2]), "=r"((R)[3]) : "r"(addr))

#define CPASYNC16(dst, src) \
    asm volatile("cp.async.cg.shared.global [%0], [%1], 16;" :: "r"(dst), "l"(src) : "memory")

__device__ __forceinline__ uint32_t pack_split(float x, float y, uint32_t& lo) {
    __nv_bfloat162 h2 = __floats2bfloat162_rn(x, y);
    float rx = x - __low2float(h2);
    float ry = y - __high2float(h2);
    __nv_bfloat162 l2 = __floats2bfloat162_rn(rx, ry);
    lo = *(uint32_t*)&l2;
    return *(uint32_t*)&h2;
}

// fp32 -> bf16 hi/lo split (vectorized)
__global__ void split_kernel(const float* __restrict__ in,
                             __nv_bfloat16* __restrict__ hi,
                             __nv_bfloat16* __restrict__ lo, int n4)
{
    int i = blockIdx.x * blockDim.x + threadIdx.x;
    if (i < n4) {
        float4 v = ((const float4*)in)[i];
        uint32_t l0, l1;
        uint32_t h0 = pack_split(v.x, v.y, l0);
        uint32_t h1 = pack_split(v.z, v.w, l1);
        ((uint2*)hi)[i] = make_uint2(h0, h1);
        ((uint2*)lo)[i] = make_uint2(l0, l1);
    }
}

// Transpose W (1024x1024, [K][N]) into K-major ([N][K]) and split hi/lo.
__global__ void transpose_split_kernel(const float* __restrict__ W,
                                       __nv_bfloat16* __restrict__ hi,
                                       __nv_bfloat16* __restrict__ lo)
{
    __shared__ float t[32][33];
    int bx = blockIdx.x * 32, by = blockIdx.y * 32;
    int x = bx + threadIdx.x;
#pragma unroll
    for (int j = 0; j < 32; j += 8)
        t[threadIdx.y + j][threadIdx.x] = W[(size_t)(by + threadIdx.y + j) * 1024 + x];
    __syncthreads();
    int k = by + threadIdx.x;
#pragma unroll
    for (int j = 0; j < 32; j += 8) {
        int n = bx + threadIdx.y + j;
        float v = t[threadIdx.x][threadIdx.y + j];
        __nv_bfloat16 h = __float2bfloat16(v);
        hi[(size_t)n * 1024 + k] = h;
        lo[(size_t)n * 1024 + k] = __float2bfloat16(v - __bfloat162float(h));
    }
}

// ---------------------------------------------------------------------------
#define NITER 96
#define WSZc ((size_t)1024*1024)

__device__ __forceinline__ uint32_t sw_off64(int row, int ch) {
    return (uint32_t)(row * 64 + ((ch ^ ((row >> 1) & 3)) << 4));
}

// ---------------------------------------------------------------------------
// Fused QKV projection: N = 3072 over [Wq|Wk|Wv]; writes bf16 hi/lo split-head.
// ---------------------------------------------------------------------------
__global__ __launch_bounds__(256, 2) void gemm_qkv_kernel(
    const __nv_bfloat16* __restrict__ Ahi, const __nv_bfloat16* __restrict__ Alo,
    const __nv_bfloat16* __restrict__ Wthi, const __nv_bfloat16* __restrict__ Wtlo,
    const float* __restrict__ bq, const float* __restrict__ bk, const float* __restrict__ bv,
    __nv_bfloat16* __restrict__ qhi, __nv_bfloat16* __restrict__ qlo,
    __nv_bfloat16* __restrict__ khi, __nv_bfloat16* __restrict__ klo,
    __nv_bfloat16* __restrict__ vhi, __nv_bfloat16* __restrict__ vlo)
{
    __shared__ __align__(1024) char smem[3 * 16384];

    const int tid = threadIdx.x;
    const int lane = tid & 31;
    const int wid = tid >> 5;
    const int wm = wid & 3;
    const int wn = wid >> 2;
    const int m0 = blockIdx.y * 128;
    const int n0 = blockIdx.x * 128;           // 0..2944
    const int j = n0 >> 10;                    // 0=q 1=k 2=v
    const uint32_t sb = smem_u32(smem);

    const __nv_bfloat16* Bhi = Wthi + (size_t)j * WSZc;
    const __nv_bfloat16* Blo = Wtlo + (size_t)j * WSZc;

    float c[2][8][4];
#pragma unroll
    for (int i = 0; i < 2; i++)
#pragma unroll
        for (int jj = 0; jj < 8; jj++)
#pragma unroll
            for (int q = 0; q < 4; q++) c[i][jj][q] = 0.0f;

    auto issue = [&](int kk) {
        int slot = kk % 3;
        int pass = kk >> 5;
        int kp = (kk & 31) * 32;
        const __nv_bfloat16* As = (pass == 2) ? Alo : Ahi;
        const __nv_bfloat16* Bs = (pass == 1) ? Blo : Bhi;
        uint32_t dA = sb + (uint32_t)slot * 16384u;
        uint32_t dB = dA + 8192u;
#pragma unroll
        for (int i = 0; i < 2; i++) {
            int id = tid + i * 256;
            int row = id >> 2, ch = id & 3;
            uint32_t so = sw_off64(row, ch);
            CPASYNC16(dA + so, As + (size_t)(m0 + row) * KK + kp + ch * 8);
            CPASYNC16(dB + so, Bs + (size_t)((n0 & 1023) + row) * KK + kp + ch * 8);
        }
        asm volatile("cp.async.commit_group;" ::: "memory");
    };

    issue(0);
    issue(1);

    for (int kk = 0; kk < NITER; kk++) {
        if (kk < NITER - 1) asm volatile("cp.async.wait_group 1;" ::: "memory");
        else                asm volatile("cp.async.wait_group 0;" ::: "memory");
        __syncthreads();
        if (kk + 2 < NITER) issue(kk + 2);

        uint32_t aBase = sb + (uint32_t)(kk % 3) * 16384u;
        uint32_t bBase = aBase + 8192u;

#pragma unroll
        for (int ks = 0; ks < 2; ks++) {
            uint32_t a[2][4];
#pragma unroll
            for (int mi = 0; mi < 2; mi++) {
                int row = wm * 32 + mi * 16 + (lane & 15);
                int ch = ks * 2 + (lane >> 4);
                LDSM4(a[mi], aBase + sw_off64(row, ch));
            }
            uint32_t b[4][4];
#pragma unroll
            for (int nj = 0; nj < 4; nj++) {
                int row = wn * 64 + nj * 16 + ((lane >> 4) << 3) + (lane & 7);
                int ch = ks * 2 + ((lane >> 3) & 1);
                LDSM4(b[nj], bBase + sw_off64(row, ch));
            }
#pragma unroll
            for (int mi = 0; mi < 2; mi++)
#pragma unroll
                for (int ni = 0; ni < 8; ni++)
                    MMA16816(c[mi][ni], a[mi],
                             b[ni >> 1][(ni & 1) * 2 + 0], b[ni >> 1][(ni & 1) * 2 + 1]);
        }
    }

    const float* bias = (j == 0) ? bq : (j == 1) ? bk : bv;
    __nv_bfloat16* ohi = (j == 0) ? qhi : (j == 1) ? khi : vhi;
    __nv_bfloat16* olo = (j == 0) ? qlo : (j == 1) ? klo : vlo;
    const float scale = (j == 0) ? 0.125f : 1.0f;

#pragma unroll
    for (int mi = 0; mi < 2; mi++) {
#pragma unroll
        for (int ni = 0; ni < 8; ni++) {
            int r0 = m0 + wm * 32 + mi * 16 + (lane >> 2);
            int nl = (n0 & 1023) + wn * 64 + ni * 8 + (lane & 3) * 2;
            float2 bvv = *(const float2*)&bias[nl];
#pragma unroll
            for (int rr = 0; rr < 2; rr++) {
                int m = r0 + rr * 8;
                float vx = (c[mi][ni][rr * 2 + 0] + bvv.x) * scale;
                float vy = (c[mi][ni][rr * 2 + 1] + bvv.y) * scale;
                int bb = m >> 11, s = m & (SS - 1);
                int h = nl >> 6, d = nl & 63;
                size_t idx = (((size_t)bb * HH + h) * SS + s) * DKK + d;
                uint32_t lo, hi = pack_split(vx, vy, lo);
                *(uint32_t*)&ohi[idx] = hi;
                *(uint32_t*)&olo[idx] = lo;
            }
        }
    }
}

// ---------------------------------------------------------------------------
// Output projection GEMM (fp32 out, row-major)
// ---------------------------------------------------------------------------
__global__ __launch_bounds__(256, 2) void gemm_out_kernel(
    const __nv_bfloat16* __restrict__ Ahi, const __nv_bfloat16* __restrict__ Alo,
    const __nv_bfloat16* __restrict__ Bhi, const __nv_bfloat16* __restrict__ Blo,
    const float* __restrict__ bias, float* __restrict__ out)
{
    __shared__ __align__(1024) char smem[3 * 16384];

    const int tid = threadIdx.x;
    const int lane = tid & 31;
    const int wid = tid >> 5;
    const int wm = wid & 3;
    const int wn = wid >> 2;
    const int m0 = blockIdx.y * 128;
    const int n0 = blockIdx.x * 128;
    const uint32_t sb = smem_u32(smem);

    float c[2][8][4];
#pragma unroll
    for (int i = 0; i < 2; i++)
#pragma unroll
        for (int jj = 0; jj < 8; jj++)
#pragma unroll
            for (int q = 0; q < 4; q++) c[i][jj][q] = 0.0f;

    auto issue = [&](int kk) {
        int slot = kk % 3;
        int pass = kk >> 5;
        int kp = (kk & 31) * 32;
        const __nv_bfloat16* As = (pass == 2) ? Alo : Ahi;
        const __nv_bfloat16* Bs = (pass == 1) ? Blo : Bhi;
        uint32_t dA = sb + (uint32_t)slot * 16384u;
        uint32_t dB = dA + 8192u;
#pragma unroll
        for (int i = 0; i < 2; i++) {
            int id = tid + i * 256;
            int row = id >> 2, ch = id & 3;
            uint32_t so = sw_off64(row, ch);
            CPASYNC16(dA + so, As + (size_t)(m0 + row) * KK + kp + ch * 8);
            CPASYNC16(dB + so, Bs + (size_t)(n0 + row) * KK + kp + ch * 8);
        }
        asm volatile("cp.async.commit_group;" ::: "memory");
    };

    issue(0);
    issue(1);

    for (int kk = 0; kk < NITER; kk++) {
        if (kk < NITER - 1) asm volatile("cp.async.wait_group 1;" ::: "memory");
        else                asm volatile("cp.async.wait_group 0;" ::: "memory");
        __syncthreads();
        if (kk + 2 < NITER) issue(kk + 2);

        uint32_t aBase = sb + (uint32_t)(kk % 3) * 16384u;
        uint32_t bBase = aBase + 8192u;

#pragma unroll
        for (int ks = 0; ks < 2; ks++) {
            uint32_t a[2][4];
#pragma unroll
            for (int mi = 0; mi < 2; mi++) {
                int row = wm * 32 + mi * 16 + (lane & 15);
                int ch = ks * 2 + (lane >> 4);
                LDSM4(a[mi], aBase + sw_off64(row, ch));
            }
            uint32_t b[4][4];
#pragma unroll
            for (int nj = 0; nj < 4; nj++) {
                int row = wn * 64 + nj * 16 + ((lane >> 4) << 3) + (lane & 7);
                int ch = ks * 2 + ((lane >> 3) & 1);
                LDSM4(b[nj], bBase + sw_off64(row, ch));
            }
#pragma unroll
            for (int mi = 0; mi < 2; mi++)
#pragma unroll
                for (int ni = 0; ni < 8; ni++)
                    MMA16816(c[mi][ni], a[mi],
                             b[ni >> 1][(ni & 1) * 2 + 0], b[ni >> 1][(ni & 1) * 2 + 1]);
        }
    }

#pragma unroll
    for (int mi = 0; mi < 2; mi++) {
#pragma unroll
        for (int ni = 0; ni < 8; ni++) {
            int r0 = m0 + wm * 32 + mi * 16 + (lane >> 2);
            int nc = n0 + wn * 64 + ni * 8 + (lane & 3) * 2;
            float2 bvv = *(const float2*)&bias[nc];
#pragma unroll
            for (int rr = 0; rr < 2; rr++) {
                int m = r0 + rr * 8;
                *(float2*)&out[(size_t)m * NN + nc] =
                    make_float2(c[mi][ni][rr * 2 + 0] + bvv.x,
                                c[mi][ni][rr * 2 + 1] + bvv.y);
            }
        }
    }
}

// ---------------------------------------------------------------------------
// HMMA flash attention: 128 q-rows/CTA, 64-key tiles, 96KB smem -> 2 CTA/SM.
// ---------------------------------------------------------------------------
__device__ __forceinline__ uint32_t sw_off128(int row, int ch) {
    return (uint32_t)(row * 128 + ((ch ^ (row & 7)) << 4));
}

#define ATTN_SMEM 98304
#define OFF_QHI 0
#define OFF_QLO 16384
#define OFF_STG 32768   /* stage s at OFF_STG + s*32768; khi,klo,vhi,vlo each 8192 */
#define NT (SS/64)      /* 32 key tiles */

__global__ __launch_bounds__(256, 2) void attn_mma_kernel(
    const __nv_bfloat16* __restrict__ Qhi, const __nv_bfloat16* __restrict__ Qlo,
    const __nv_bfloat16* __restrict__ Khi, const __nv_bfloat16* __restrict__ Klo,
    const __nv_bfloat16* __restrict__ Vhi, const __nv_bfloat16* __restrict__ Vlo,
    __nv_bfloat16* __restrict__ Chi, __nv_bfloat16* __restrict__ Clo)
{
    extern __shared__ __align__(1024) char dsm[];
    const uint32_t sb = smem_u32(dsm);

    const int tid = threadIdx.x;
    const int lane = tid & 31;
    const int wm = tid >> 5;
    const int b = blockIdx.z, h = blockIdx.y;
    const int q0 = blockIdx.x * 128;
    const size_t base = ((size_t)b * HH + h) * SS * DKK;

    // ---- Q loads (group 0)
    {
        uint32_t dh = sb + OFF_QHI, dl = sb + OFF_QLO;
#pragma unroll
        for (int i = 0; i < 4; i++) {
            int id = tid + i * 256;
            int row = id >> 3, ch = id & 7;
            uint32_t so = sw_off128(row, ch);
            CPASYNC16(dh + so, Qhi + base + (size_t)(q0 + row) * DKK + ch * 8);
            CPASYNC16(dl + so, Qlo + base + (size_t)(q0 + row) * DKK + ch * 8);
        }
        asm volatile("cp.async.commit_group;" ::: "memory");
    }

    auto issue_kv = [&](int t, int stg) {
        uint32_t st = sb + OFF_STG + (uint32_t)stg * 32768u;
        const __nv_bfloat16* bufs[4] = {Khi, Klo, Vhi, Vlo};
#pragma unroll
        for (int bu = 0; bu < 4; bu++) {
            uint32_t dst = st + (uint32_t)bu * 8192u;
            const __nv_bfloat16* src = bufs[bu];
#pragma unroll
            for (int i = 0; i < 2; i++) {
                int id = tid + i * 256;
                int row = id >> 3, ch = id & 7;
                CPASYNC16(dst + sw_off128(row, ch),
                          src + base + (size_t)(t * 64 + row) * DKK + ch * 8);
            }
        }
        asm volatile("cp.async.commit_group;" ::: "memory");
    };

    issue_kv(0, 0);
    issue_kv(1, 1);

    asm volatile("cp.async.wait_group 2;" ::: "memory");
    __syncthreads();

    uint32_t qh[4][4], ql[4][4];
#pragma unroll
    for (int ks = 0; ks < 4; ks++) {
        int row = wm * 16 + (lane & 15);
        int ch = ks * 2 + (lane >> 4);
        LDSM4(qh[ks], sb + OFF_QHI + sw_off128(row, ch));
        LDSM4(ql[ks], sb + OFF_QLO + sw_off128(row, ch));
    }

    float o[8][4];
#pragma unroll
    for (int i = 0; i < 8; i++)
#pragma unroll
        for (int j = 0; j < 4; j++) o[i][j] = 0.0f;
    float m0 = -1e30f, m1 = -1e30f, l0 = 0.0f, l1 = 0.0f;

    for (int t = 0; t < NT; t++) {
        if (t < NT - 1) asm volatile("cp.async.wait_group 1;" ::: "memory");
        else            asm volatile("cp.async.wait_group 0;" ::: "memory");
        __syncthreads();

        uint32_t st = sb + OFF_STG + (uint32_t)(t & 1) * 32768u;
        uint32_t kh = st, kl = st + 8192u, vh = st + 16384u, vl = st + 24576u;

        // ---- S = Qhi*Khi + Qlo*Khi + Qhi*Klo   (64 keys)
        float s[8][4];
#pragma unroll
        for (int i = 0; i < 8; i++)
#pragma unroll
            for (int j = 0; j < 4; j++) s[i][j] = 0.0f;

#pragma unroll
        for (int ks = 0; ks < 4; ks++) {
#pragma unroll
            for (int nj = 0; nj < 4; nj++) {
                int row = nj * 16 + ((lane >> 4) << 3) + (lane & 7);
                int ch = ks * 2 + ((lane >> 3) & 1);
                uint32_t bh[4], bl[4];
                LDSM4(bh, kh + sw_off128(row, ch));
                LDSM4(bl, kl + sw_off128(row, ch));
#pragma unroll
                for (int half = 0; half < 2; half++) {
                    int ni = nj * 2 + half;
                    uint32_t b0 = bh[half * 2], b1 = bh[half * 2 + 1];
                    MMA16816(s[ni], qh[ks], b0, b1);
                    MMA16816(s[ni], ql[ks], b0, b1);
                    MMA16816(s[ni], qh[ks], bl[half * 2], bl[half * 2 + 1]);
                }
            }
        }

        // ---- online softmax
        float mt0 = -1e30f, mt1 = -1e30f;
#pragma unroll
        for (int ni = 0; ni < 8; ni++) {
            mt0 = fmaxf(mt0, fmaxf(s[ni][0], s[ni][1]));
            mt1 = fmaxf(mt1, fmaxf(s[ni][2], s[ni][3]));
        }
        mt0 = fmaxf(mt0, __shfl_xor_sync(0xffffffffu, mt0, 1));
        mt0 = fmaxf(mt0, __shfl_xor_sync(0xffffffffu, mt0, 2));
        mt1 = fmaxf(mt1, __shfl_xor_sync(0xffffffffu, mt1, 1));
        mt1 = fmaxf(mt1, __shfl_xor_sync(0xffffffffu, mt1, 2));
        float mn0 = fmaxf(m0, mt0), mn1 = fmaxf(m1, mt1);
        float a0 = __expf(m0 - mn0), a1 = __expf(m1 - mn1);
        float ps0 = 0.0f, ps1 = 0.0f;
#pragma unroll
        for (int ni = 0; ni < 8; ni++) {
            s[ni][0] = __expf(s[ni][0] - mn0);
            s[ni][1] = __expf(s[ni][1] - mn0);
            s[ni][2] = __expf(s[ni][2] - mn1);
            s[ni][3] = __expf(s[ni][3] - mn1);
            ps0 += s[ni][0] + s[ni][1];
            ps1 += s[ni][2] + s[ni][3];
        }
        ps0 += __shfl_xor_sync(0xffffffffu, ps0, 1);
        ps0 += __shfl_xor_sync(0xffffffffu, ps0, 2);
        ps1 += __shfl_xor_sync(0xffffffffu, ps1, 1);
        ps1 += __shfl_xor_sync(0xffffffffu, ps1, 2);
        l0 = l0 * a0 + ps0; l1 = l1 * a1 + ps1;
        m0 = mn0; m1 = mn1;
#pragma unroll
        for (int ni = 0; ni < 8; ni++) {
            o[ni][0] *= a0; o[ni][1] *= a0;
            o[ni][2] *= a1; o[ni][3] *= a1;
        }

        // ---- O += P*V  (phi*vhi + plo*vhi + phi*vlo)
#pragma unroll
        for (int kb = 0; kb < 4; kb++) {
            uint32_t ph[4], pl[4];
            ph[0] = pack_split(s[2*kb][0],   s[2*kb][1],   pl[0]);
            ph[1] = pack_split(s[2*kb][2],   s[2*kb][3],   pl[1]);
            ph[2] = pack_split(s[2*kb+1][0], s[2*kb+1][1], pl[2]);
            ph[3] = pack_split(s[2*kb+1][2], s[2*kb+1][3], pl[3]);
#pragma unroll
            for (int dj = 0; dj < 4; dj++) {
                int qm = lane >> 3;
                int row = kb * 16 + (qm & 1) * 8 + (lane & 7);
                int ch = dj * 2 + (qm >> 1);
                uint32_t vr[4], vlr[4];
                LDSM4T(vr,  vh + sw_off128(row, ch));
                LDSM4T(vlr, vl + sw_off128(row, ch));
#pragma unroll
                for (int half = 0; half < 2; half++) {
                    int ni = dj * 2 + half;
                    uint32_t b0 = vr[half * 2], b1 = vr[half * 2 + 1];
                    MMA16816(o[ni], ph, b0, b1);
                    MMA16816(o[ni], pl, b0, b1);
                    MMA16816(o[ni], ph, vlr[half * 2], vlr[half * 2 + 1]);
                }
            }
        }

        __syncthreads();
        if (t + 2 < NT) issue_kv(t + 2, t & 1);
    }

    // ---- epilogue
    float inv0 = 1.0f / l0, inv1 = 1.0f / l1;
    int srow0 = q0 + wm * 16 + (lane >> 2);
#pragma unroll
    for (int ni = 0; ni < 8; ni++) {
        int d = ni * 8 + (lane & 3) * 2;
        size_t i0 = ((size_t)b * SS + srow0) * NN + h * DKK + d;
        size_t i1 = ((size_t)b * SS + srow0 + 8) * NN + h * DKK + d;
        uint32_t lo, hi;
        hi = pack_split(o[ni][0] * inv0, o[ni][1] * inv0, lo);
        *(uint32_t*)&Chi[i0] = hi;  *(uint32_t*)&Clo[i0] = lo;
        hi = pack_split(o[ni][2] * inv1, o[ni][3] * inv1, lo);
        *(uint32_t*)&Chi[i1] = hi;  *(uint32_t*)&Clo[i1] = lo;
    }
}

// ---------------------------------------------------------------------------
extern "C" void kernel_launch(void* const* d_in, const int* in_sizes, int n_in,
                              void* d_out, int out_size)
{
    const float* x  = (const float*)d_in[0];
    const float* Wq = (const float*)d_in[1];
    const float* bq = (const float*)d_in[2];
    const float* Wk = (const float*)d_in[3];
    const float* bk = (const float*)d_in[4];
    const float* Wv = (const float*)d_in[5];
    const float* bv = (const float*)d_in[6];
    const float* Wo = (const float*)d_in[7];
    const float* bo = (const float*)d_in[8];
    float* out = (float*)d_out;

    __nv_bfloat16 *qhi, *qlo, *khi, *klo, *vhi, *vlo, *xhi, *xlo, *chi, *clo, *wthi, *wtlo;
    cudaGetSymbolAddress((void**)&qhi, g_qhi);
    cudaGetSymbolAddress((void**)&qlo, g_qlo);
    cudaGetSymbolAddress((void**)&khi, g_khi);
    cudaGetSymbolAddress((void**)&klo, g_klo);
    cudaGetSymbolAddress((void**)&vhi, g_vhi);
    cudaGetSymbolAddress((void**)&vlo, g_vlo);
    cudaGetSymbolAddress((void**)&xhi, g_xhi);
    cudaGetSymbolAddress((void**)&xlo, g_xlo);
    cudaGetSymbolAddress((void**)&chi, g_chi);
    cudaGetSymbolAddress((void**)&clo, g_clo);
    cudaGetSymbolAddress((void**)&wthi, g_wthi);
    cudaGetSymbolAddress((void**)&wtlo, g_wtlo);

    cudaFuncSetAttribute(attn_mma_kernel, cudaFuncAttributeMaxDynamicSharedMemorySize, ATTN_SMEM);

    split_kernel<<<(MM * KK / 4 + 255) / 256, 256>>>(x, xhi, xlo, MM * KK / 4);

    dim3 tgrid(32, 32), tblk(32, 8);
    transpose_split_kernel<<<tgrid, tblk>>>(Wq, wthi + 0 * WSZc, wtlo + 0 * WSZc);
    transpose_split_kernel<<<tgrid, tblk>>>(Wk, wthi + 1 * WSZc, wtlo + 1 * WSZc);
    transpose_split_kernel<<<tgrid, tblk>>>(Wv, wthi + 2 * WSZc, wtlo + 2 * WSZc);
    transpose_split_kernel<<<tgrid, tblk>>>(Wo, wthi + 3 * WSZc, wtlo + 3 * WSZc);

    gemm_qkv_kernel<<<dim3(24, 64), 256>>>(xhi, xlo, wthi, wtlo, bq, bk, bv,
                                           qhi, qlo, khi, klo, vhi, vlo);

    attn_mma_kernel<<<dim3(SS / 128, HH, BB), 256, ATTN_SMEM>>>(
        qhi, qlo, khi, klo, vhi, vlo, chi, clo);

    gemm_out_kernel<<<dim3(8, 64), 256>>>(chi, clo, wthi + 3 * WSZc, wtlo + 3 * WSZc, bo, out);
}

// round 7
// speedup vs baseline: 11.1784x; 2.4668x over previous
#include <cuda_runtime.h>
#include <cuda_fp16.h>
#include <cstdint>
#include <math.h>

#define BB 4
#define SS 2048
#define EE 1024
#define HH 16
#define DKK 64
#define MM (BB*SS)      /* 8192 */
#define NN (HH*DKK)     /* 1024 */
#define KK EE           /* 1024 */

// ---------------------------------------------------------------------------
// Scratch (device globals — no allocation allowed)
// ---------------------------------------------------------------------------
__device__ __half g_q[(size_t)MM*NN];
__device__ __half g_k[(size_t)MM*NN];
__device__ __half g_v[(size_t)MM*NN];
__device__ __half g_x[(size_t)MM*KK];
__device__ __half g_c[(size_t)MM*NN];
__device__ __half g_wt[(size_t)4*1024*1024];

// ---------------------------------------------------------------------------
__device__ __forceinline__ uint32_t smem_u32(const void* p) {
    uint32_t a;
    asm("{ .reg .u64 t; cvta.to.shared.u64 t, %1; cvt.u32.u64 %0, t; }"
        : "=r"(a) : "l"(p));
    return a;
}

#define MMA16816(C, A, B0, B1) \
    asm volatile("mma.sync.aligned.m16n8k16.row.col.f32.f16.f16.f32 " \
                 "{%0,%1,%2,%3}, {%4,%5,%6,%7}, {%8,%9}, {%0,%1,%2,%3};" \
                 : "+f"((C)[0]), "+f"((C)[1]), "+f"((C)[2]), "+f"((C)[3]) \
                 : "r"((A)[0]), "r"((A)[1]), "r"((A)[2]), "r"((A)[3]), \
                   "r"(B0), "r"(B1))

#define LDSM4(R, addr) \
    asm volatile("ldmatrix.sync.aligned.m8n8.x4.shared.b16 {%0,%1,%2,%3}, [%4];" \
                 : "=r"((R)[0]), "=r"((R)[1]), "=r"((R)[2]), "=r"((R)[3]) : "r"(addr))

#define LDSM4T(R, addr) \
    asm volatile("ldmatrix.sync.aligned.m8n8.x4.trans.shared.b16 {%0,%1,%2,%3}, [%4];" \
                 : "=r"((R)[0]), "=r"((R)[1]), "=r"((R)[2]), "=r"((R)[3]) : "r"(addr))

#define CPASYNC16(dst, src) \
    asm volatile("cp.async.cg.shared.global [%0], [%1], 16;" :: "r"(dst), "l"(src) : "memory")

__device__ __forceinline__ uint32_t pack_f16(float x, float y) {
    __half2 h2 = __floats2half2_rn(x, y);
    return *(uint32_t*)&h2;
}

// fp32 -> fp16 (vectorized)
__global__ void tof16_kernel(const float* __restrict__ in,
                             __half* __restrict__ o, int n4)
{
    int i = blockIdx.x * blockDim.x + threadIdx.x;
    if (i < n4) {
        float4 v = ((const float4*)in)[i];
        ((uint2*)o)[i] = make_uint2(pack_f16(v.x, v.y), pack_f16(v.z, v.w));
    }
}

// Transpose W [K][N] -> [N][K] fp16
__global__ void transpose_f16_kernel(const float* __restrict__ W,
                                     __half* __restrict__ o)
{
    __shared__ float t[32][33];
    int bx = blockIdx.x * 32, by = blockIdx.y * 32;
    int x = bx + threadIdx.x;
#pragma unroll
    for (int j = 0; j < 32; j += 8)
        t[threadIdx.y + j][threadIdx.x] = W[(size_t)(by + threadIdx.y + j) * 1024 + x];
    __syncthreads();
    int k = by + threadIdx.x;
#pragma unroll
    for (int j = 0; j < 32; j += 8) {
        int n = bx + threadIdx.y + j;
        o[(size_t)n * 1024 + k] = __float2half(t[threadIdx.x][threadIdx.y + j]);
    }
}

// ---------------------------------------------------------------------------
#define WSZc ((size_t)1024*1024)

__device__ __forceinline__ uint32_t sw_off64(int row, int ch) {
    return (uint32_t)(row * 64 + ((ch ^ ((row >> 1) & 3)) << 4));
}

// ---------------------------------------------------------------------------
// Fused QKV projection, 1-pass fp16: N = 3072 over [Wq|Wk|Wv].
// ---------------------------------------------------------------------------
__global__ __launch_bounds__(256, 2) void gemm_qkv_kernel(
    const __half* __restrict__ Ah,
    const __half* __restrict__ Wth,
    const float* __restrict__ bq, const float* __restrict__ bk, const float* __restrict__ bv,
    __half* __restrict__ qo, __half* __restrict__ ko, __half* __restrict__ vo)
{
    __shared__ __align__(1024) char smem[3 * 16384];

    const int tid = threadIdx.x;
    const int lane = tid & 31;
    const int wid = tid >> 5;
    const int wm = wid & 3;
    const int wn = wid >> 2;
    const int m0 = blockIdx.y * 128;
    const int n0 = blockIdx.x * 128;
    const int j = n0 >> 10;
    const uint32_t sb = smem_u32(smem);

    const __half* Bh = Wth + (size_t)j * WSZc;

    float c[2][8][4];
#pragma unroll
    for (int i = 0; i < 2; i++)
#pragma unroll
        for (int jj = 0; jj < 8; jj++)
#pragma unroll
            for (int q = 0; q < 4; q++) c[i][jj][q] = 0.0f;

    auto issue = [&](int kk) {
        int slot = kk % 3;
        int kp = kk * 32;
        uint32_t dA = sb + (uint32_t)slot * 16384u;
        uint32_t dB = dA + 8192u;
#pragma unroll
        for (int i = 0; i < 2; i++) {
            int id = tid + i * 256;
            int row = id >> 2, ch = id & 3;
            uint32_t so = sw_off64(row, ch);
            CPASYNC16(dA + so, Ah + (size_t)(m0 + row) * KK + kp + ch * 8);
            CPASYNC16(dB + so, Bh + (size_t)((n0 & 1023) + row) * KK + kp + ch * 8);
        }
        asm volatile("cp.async.commit_group;" ::: "memory");
    };

    issue(0);
    issue(1);

    for (int kk = 0; kk < 32; kk++) {
        if (kk < 31) asm volatile("cp.async.wait_group 1;" ::: "memory");
        else         asm volatile("cp.async.wait_group 0;" ::: "memory");
        __syncthreads();
        if (kk + 2 < 32) issue(kk + 2);

        uint32_t aBase = sb + (uint32_t)(kk % 3) * 16384u;
        uint32_t bBase = aBase + 8192u;

#pragma unroll
        for (int ks = 0; ks < 2; ks++) {
            uint32_t a[2][4];
#pragma unroll
            for (int mi = 0; mi < 2; mi++) {
                int row = wm * 32 + mi * 16 + (lane & 15);
                int ch = ks * 2 + (lane >> 4);
                LDSM4(a[mi], aBase + sw_off64(row, ch));
            }
            uint32_t b[4][4];
#pragma unroll
            for (int nj = 0; nj < 4; nj++) {
                int row = wn * 64 + nj * 16 + ((lane >> 4) << 3) + (lane & 7);
                int ch = ks * 2 + ((lane >> 3) & 1);
                LDSM4(b[nj], bBase + sw_off64(row, ch));
            }
#pragma unroll
            for (int mi = 0; mi < 2; mi++)
#pragma unroll
                for (int ni = 0; ni < 8; ni++)
                    MMA16816(c[mi][ni], a[mi],
                             b[ni >> 1][(ni & 1) * 2 + 0], b[ni >> 1][(ni & 1) * 2 + 1]);
        }
    }

    const float* bias = (j == 0) ? bq : (j == 1) ? bk : bv;
    __half* oh = (j == 0) ? qo : (j == 1) ? ko : vo;
    const float scale = (j == 0) ? 0.125f : 1.0f;

#pragma unroll
    for (int mi = 0; mi < 2; mi++) {
#pragma unroll
        for (int ni = 0; ni < 8; ni++) {
            int r0 = m0 + wm * 32 + mi * 16 + (lane >> 2);
            int nl = (n0 & 1023) + wn * 64 + ni * 8 + (lane & 3) * 2;
            float2 bvv = *(const float2*)&bias[nl];
#pragma unroll
            for (int rr = 0; rr < 2; rr++) {
                int m = r0 + rr * 8;
                float vx = (c[mi][ni][rr * 2 + 0] + bvv.x) * scale;
                float vy = (c[mi][ni][rr * 2 + 1] + bvv.y) * scale;
                int bb = m >> 11, s = m & (SS - 1);
                int h = nl >> 6, d = nl & 63;
                size_t idx = (((size_t)bb * HH + h) * SS + s) * DKK + d;
                *(uint32_t*)&oh[idx] = pack_f16(vx, vy);
            }
        }
    }
}

// ---------------------------------------------------------------------------
// Output projection GEMM, 1-pass fp16, fp32 out.
// ---------------------------------------------------------------------------
__global__ __launch_bounds__(256, 2) void gemm_out_kernel(
    const __half* __restrict__ Ah, const __half* __restrict__ Bh,
    const float* __restrict__ bias, float* __restrict__ out)
{
    __shared__ __align__(1024) char smem[3 * 16384];

    const int tid = threadIdx.x;
    const int lane = tid & 31;
    const int wid = tid >> 5;
    const int wm = wid & 3;
    const int wn = wid >> 2;
    const int m0 = blockIdx.y * 128;
    const int n0 = blockIdx.x * 128;
    const uint32_t sb = smem_u32(smem);

    float c[2][8][4];
#pragma unroll
    for (int i = 0; i < 2; i++)
#pragma unroll
        for (int jj = 0; jj < 8; jj++)
#pragma unroll
            for (int q = 0; q < 4; q++) c[i][jj][q] = 0.0f;

    auto issue = [&](int kk) {
        int slot = kk % 3;
        int kp = kk * 32;
        uint32_t dA = sb + (uint32_t)slot * 16384u;
        uint32_t dB = dA + 8192u;
#pragma unroll
        for (int i = 0; i < 2; i++) {
            int id = tid + i * 256;
            int row = id >> 2, ch = id & 3;
            uint32_t so = sw_off64(row, ch);
            CPASYNC16(dA + so, Ah + (size_t)(m0 + row) * KK + kp + ch * 8);
            CPASYNC16(dB + so, Bh + (size_t)(n0 + row) * KK + kp + ch * 8);
        }
        asm volatile("cp.async.commit_group;" ::: "memory");
    };

    issue(0);
    issue(1);

    for (int kk = 0; kk < 32; kk++) {
        if (kk < 31) asm volatile("cp.async.wait_group 1;" ::: "memory");
        else         asm volatile("cp.async.wait_group 0;" ::: "memory");
        __syncthreads();
        if (kk + 2 < 32) issue(kk + 2);

        uint32_t aBase = sb + (uint32_t)(kk % 3) * 16384u;
        uint32_t bBase = aBase + 8192u;

#pragma unroll
        for (int ks = 0; ks < 2; ks++) {
            uint32_t a[2][4];
#pragma unroll
            for (int mi = 0; mi < 2; mi++) {
                int row = wm * 32 + mi * 16 + (lane & 15);
                int ch = ks * 2 + (lane >> 4);
                LDSM4(a[mi], aBase + sw_off64(row, ch));
            }
            uint32_t b[4][4];
#pragma unroll
            for (int nj = 0; nj < 4; nj++) {
                int row = wn * 64 + nj * 16 + ((lane >> 4) << 3) + (lane & 7);
                int ch = ks * 2 + ((lane >> 3) & 1);
                LDSM4(b[nj], bBase + sw_off64(row, ch));
            }
#pragma unroll
            for (int mi = 0; mi < 2; mi++)
#pragma unroll
                for (int ni = 0; ni < 8; ni++)
                    MMA16816(c[mi][ni], a[mi],
                             b[ni >> 1][(ni & 1) * 2 + 0], b[ni >> 1][(ni & 1) * 2 + 1]);
        }
    }

#pragma unroll
    for (int mi = 0; mi < 2; mi++) {
#pragma unroll
        for (int ni = 0; ni < 8; ni++) {
            int r0 = m0 + wm * 32 + mi * 16 + (lane >> 2);
            int nc = n0 + wn * 64 + ni * 8 + (lane & 3) * 2;
            float2 bvv = *(const float2*)&bias[nc];
#pragma unroll
            for (int rr = 0; rr < 2; rr++) {
                int m = r0 + rr * 8;
                *(float2*)&out[(size_t)m * NN + nc] =
                    make_float2(c[mi][ni][rr * 2 + 0] + bvv.x,
                                c[mi][ni][rr * 2 + 1] + bvv.y);
            }
        }
    }
}

// ---------------------------------------------------------------------------
// HMMA flash attention, fp16 single-pass QK and PV.
// 128 q-rows/CTA, 64-key tiles, 4-stage pipeline, 80KB smem -> 2 CTA/SM.
// ---------------------------------------------------------------------------
__device__ __forceinline__ uint32_t sw_off128(int row, int ch) {
    return (uint32_t)(row * 128 + ((ch ^ (row & 7)) << 4));
}

#define ATTN_SMEM 81920
#define OFF_Q 0
#define OFF_STG 16384   /* stage s at OFF_STG + s*16384; kh 8192, vh 8192 */
#define NT (SS/64)      /* 32 key tiles */

__global__ __launch_bounds__(256, 2) void attn_mma_kernel(
    const __half* __restrict__ Q, const __half* __restrict__ K,
    const __half* __restrict__ V, __half* __restrict__ C)
{
    extern __shared__ __align__(1024) char dsm[];
    const uint32_t sb = smem_u32(dsm);

    const int tid = threadIdx.x;
    const int lane = tid & 31;
    const int wm = tid >> 5;
    const int b = blockIdx.z, h = blockIdx.y;
    const int q0 = blockIdx.x * 128;
    const size_t base = ((size_t)b * HH + h) * SS * DKK;

    // ---- Q loads (group 0)
    {
        uint32_t dq = sb + OFF_Q;
#pragma unroll
        for (int i = 0; i < 4; i++) {
            int id = tid + i * 256;
            int row = id >> 3, ch = id & 7;
            CPASYNC16(dq + sw_off128(row, ch), Q + base + (size_t)(q0 + row) * DKK + ch * 8);
        }
        asm volatile("cp.async.commit_group;" ::: "memory");
    }

    auto issue_kv = [&](int t) {
        uint32_t st = sb + OFF_STG + (uint32_t)(t & 3) * 16384u;
#pragma unroll
        for (int i = 0; i < 2; i++) {
            int id = tid + i * 256;
            int row = id >> 3, ch = id & 7;
            uint32_t so = sw_off128(row, ch);
            CPASYNC16(st + so,         K + base + (size_t)(t * 64 + row) * DKK + ch * 8);
            CPASYNC16(st + 8192u + so, V + base + (size_t)(t * 64 + row) * DKK + ch * 8);
        }
        asm volatile("cp.async.commit_group;" ::: "memory");
    };

    issue_kv(0);
    issue_kv(1);
    issue_kv(2);

    asm volatile("cp.async.wait_group 3;" ::: "memory");
    __syncthreads();

    uint32_t qh[4][4];
#pragma unroll
    for (int ks = 0; ks < 4; ks++) {
        int row = wm * 16 + (lane & 15);
        int ch = ks * 2 + (lane >> 4);
        LDSM4(qh[ks], sb + OFF_Q + sw_off128(row, ch));
    }

    float o[8][4];
#pragma unroll
    for (int i = 0; i < 8; i++)
#pragma unroll
        for (int j = 0; j < 4; j++) o[i][j] = 0.0f;
    float m0 = -1e30f, m1 = -1e30f, l0 = 0.0f, l1 = 0.0f;

    for (int t = 0; t < NT; t++) {
        if (t <= NT - 3)      asm volatile("cp.async.wait_group 2;" ::: "memory");
        else if (t == NT - 2) asm volatile("cp.async.wait_group 1;" ::: "memory");
        else                  asm volatile("cp.async.wait_group 0;" ::: "memory");
        __syncthreads();
        if (t + 3 < NT) issue_kv(t + 3);

        uint32_t st = sb + OFF_STG + (uint32_t)(t & 3) * 16384u;
        uint32_t kh = st, vh = st + 8192u;

        // ---- S = Q @ K^T (fp16 single pass, 64 keys)
        float s[8][4];
#pragma unroll
        for (int i = 0; i < 8; i++)
#pragma unroll
            for (int j = 0; j < 4; j++) s[i][j] = 0.0f;

#pragma unroll
        for (int ks = 0; ks < 4; ks++) {
#pragma unroll
            for (int nj = 0; nj < 4; nj++) {
                int row = nj * 16 + ((lane >> 4) << 3) + (lane & 7);
                int ch = ks * 2 + ((lane >> 3) & 1);
                uint32_t bh[4];
                LDSM4(bh, kh + sw_off128(row, ch));
#pragma unroll
                for (int half = 0; half < 2; half++)
                    MMA16816(s[nj * 2 + half], qh[ks], bh[half * 2], bh[half * 2 + 1]);
            }
        }

        // ---- online softmax
        float mt0 = -1e30f, mt1 = -1e30f;
#pragma unroll
        for (int ni = 0; ni < 8; ni++) {
            mt0 = fmaxf(mt0, fmaxf(s[ni][0], s[ni][1]));
            mt1 = fmaxf(mt1, fmaxf(s[ni][2], s[ni][3]));
        }
        mt0 = fmaxf(mt0, __shfl_xor_sync(0xffffffffu, mt0, 1));
        mt0 = fmaxf(mt0, __shfl_xor_sync(0xffffffffu, mt0, 2));
        mt1 = fmaxf(mt1, __shfl_xor_sync(0xffffffffu, mt1, 1));
        mt1 = fmaxf(mt1, __shfl_xor_sync(0xffffffffu, mt1, 2));
        float mn0 = fmaxf(m0, mt0), mn1 = fmaxf(m1, mt1);
        float a0 = __expf(m0 - mn0), a1 = __expf(m1 - mn1);
        float ps0 = 0.0f, ps1 = 0.0f;
#pragma unroll
        for (int ni = 0; ni < 8; ni++) {
            s[ni][0] = __expf(s[ni][0] - mn0);
            s[ni][1] = __expf(s[ni][1] - mn0);
            s[ni][2] = __expf(s[ni][2] - mn1);
            s[ni][3] = __expf(s[ni][3] - mn1);
            ps0 += s[ni][0] + s[ni][1];
            ps1 += s[ni][2] + s[ni][3];
        }
        ps0 += __shfl_xor_sync(0xffffffffu, ps0, 1);
        ps0 += __shfl_xor_sync(0xffffffffu, ps0, 2);
        ps1 += __shfl_xor_sync(0xffffffffu, ps1, 1);
        ps1 += __shfl_xor_sync(0xffffffffu, ps1, 2);
        l0 = l0 * a0 + ps0; l1 = l1 * a1 + ps1;
        m0 = mn0; m1 = mn1;
#pragma unroll
        for (int ni = 0; ni < 8; ni++) {
            o[ni][0] *= a0; o[ni][1] *= a0;
            o[ni][2] *= a1; o[ni][3] *= a1;
        }

        // ---- O += P @ V (fp16 single pass)
#pragma unroll
        for (int kb = 0; kb < 4; kb++) {
            uint32_t ph[4];
            ph[0] = pack_f16(s[2*kb][0],   s[2*kb][1]);
            ph[1] = pack_f16(s[2*kb][2],   s[2*kb][3]);
            ph[2] = pack_f16(s[2*kb+1][0], s[2*kb+1][1]);
            ph[3] = pack_f16(s[2*kb+1][2], s[2*kb+1][3]);
#pragma unroll
            for (int dj = 0; dj < 4; dj++) {
                int qm = lane >> 3;
                int row = kb * 16 + (qm & 1) * 8 + (lane & 7);
                int ch = dj * 2 + (qm >> 1);
                uint32_t vr[4];
                LDSM4T(vr, vh + sw_off128(row, ch));
#pragma unroll
                for (int half = 0; half < 2; half++)
                    MMA16816(o[dj * 2 + half], ph, vr[half * 2], vr[half * 2 + 1]);
            }
        }
    }

    // ---- epilogue: normalize, store ctx fp16 [b][s][h*64+d]
    float inv0 = 1.0f / l0, inv1 = 1.0f / l1;
    int srow0 = q0 + wm * 16 + (lane >> 2);
#pragma unroll
    for (int ni = 0; ni < 8; ni++) {
        int d = ni * 8 + (lane & 3) * 2;
        size_t i0 = ((size_t)b * SS + srow0) * NN + h * DKK + d;
        size_t i1 = ((size_t)b * SS + srow0 + 8) * NN + h * DKK + d;
        *(uint32_t*)&C[i0] = pack_f16(o[ni][0] * inv0, o[ni][1] * inv0);
        *(uint32_t*)&C[i1] = pack_f16(o[ni][2] * inv1, o[ni][3] * inv1);
    }
}

// ---------------------------------------------------------------------------
extern "C" void kernel_launch(void* const* d_in, const int* in_sizes, int n_in,
                              void* d_out, int out_size)
{
    const float* x  = (const float*)d_in[0];
    const float* Wq = (const float*)d_in[1];
    const float* bq = (const float*)d_in[2];
    const float* Wk = (const float*)d_in[3];
    const float* bk = (const float*)d_in[4];
    const float* Wv = (const float*)d_in[5];
    const float* bv = (const float*)d_in[6];
    const float* Wo = (const float*)d_in[7];
    const float* bo = (const float*)d_in[8];
    float* out = (float*)d_out;

    __half *q, *k, *v, *xh, *c, *wt;
    cudaGetSymbolAddress((void**)&q, g_q);
    cudaGetSymbolAddress((void**)&k, g_k);
    cudaGetSymbolAddress((void**)&v, g_v);
    cudaGetSymbolAddress((void**)&xh, g_x);
    cudaGetSymbolAddress((void**)&c, g_c);
    cudaGetSymbolAddress((void**)&wt, g_wt);

    cudaFuncSetAttribute(attn_mma_kernel, cudaFuncAttributeMaxDynamicSharedMemorySize, ATTN_SMEM);

    tof16_kernel<<<(MM * KK / 4 + 255) / 256, 256>>>(x, xh, MM * KK / 4);

    dim3 tgrid(32, 32), tblk(32, 8);
    transpose_f16_kernel<<<tgrid, tblk>>>(Wq, wt + 0 * WSZc);
    transpose_f16_kernel<<<tgrid, tblk>>>(Wk, wt + 1 * WSZc);
    transpose_f16_kernel<<<tgrid, tblk>>>(Wv, wt + 2 * WSZc);
    transpose_f16_kernel<<<tgrid, tblk>>>(Wo, wt + 3 * WSZc);

    gemm_qkv_kernel<<<dim3(24, 64), 256>>>(xh, wt, bq, bk, bv, q, k, v);

    attn_mma_kernel<<<dim3(SS / 128, HH, BB), 256, ATTN_SMEM>>>(q, k, v, c);

    gemm_out_kernel<<<dim3(8, 64), 256>>>(c, wt + 3 * WSZc, bo, out);
}

// round 8
// speedup vs baseline: 11.5490x; 1.0332x over previous
#include <cuda_runtime.h>
#include <cuda_fp16.h>
#include <cstdint>
#include <math.h>

#define BB 4
#define SS 2048
#define EE 1024
#define HH 16
#define DKK 64
#define MM (BB*SS)      /* 8192 */
#define NN (HH*DKK)     /* 1024 */
#define KK EE           /* 1024 */

/* Q scale folded with log2(e): softmax computed in base-2 domain. */
#define QSCALE 0.18033688f   /* 0.125 * 1.44269504 */

// ---------------------------------------------------------------------------
// Scratch (device globals — no allocation allowed)
// ---------------------------------------------------------------------------
__device__ __half g_q[(size_t)MM*NN];
__device__ __half g_k[(size_t)MM*NN];
__device__ __half g_v[(size_t)MM*NN];
__device__ __half g_x[(size_t)MM*KK];
__device__ __half g_c[(size_t)MM*NN];
__device__ __half g_wt[(size_t)4*1024*1024];

// ---------------------------------------------------------------------------
__device__ __forceinline__ uint32_t smem_u32(const void* p) {
    uint32_t a;
    asm("{ .reg .u64 t; cvta.to.shared.u64 t, %1; cvt.u32.u64 %0, t; }"
        : "=r"(a) : "l"(p));
    return a;
}

#define MMA16816(C, A, B0, B1) \
    asm volatile("mma.sync.aligned.m16n8k16.row.col.f32.f16.f16.f32 " \
                 "{%0,%1,%2,%3}, {%4,%5,%6,%7}, {%8,%9}, {%0,%1,%2,%3};" \
                 : "+f"((C)[0]), "+f"((C)[1]), "+f"((C)[2]), "+f"((C)[3]) \
                 : "r"((A)[0]), "r"((A)[1]), "r"((A)[2]), "r"((A)[3]), \
                   "r"(B0), "r"(B1))

#define LDSM4(R, addr) \
    asm volatile("ldmatrix.sync.aligned.m8n8.x4.shared.b16 {%0,%1,%2,%3}, [%4];" \
                 : "=r"((R)[0]), "=r"((R)[1]), "=r"((R)[2]), "=r"((R)[3]) : "r"(addr))

#define LDSM4T(R, addr) \
    asm volatile("ldmatrix.sync.aligned.m8n8.x4.trans.shared.b16 {%0,%1,%2,%3}, [%4];" \
                 : "=r"((R)[0]), "=r"((R)[1]), "=r"((R)[2]), "=r"((R)[3]) : "r"(addr))

#define CPASYNC16(dst, src) \
    asm volatile("cp.async.cg.shared.global [%0], [%1], 16;" :: "r"(dst), "l"(src) : "memory")

__device__ __forceinline__ uint32_t pack_f16(float x, float y) {
    __half2 h2 = __floats2half2_rn(x, y);
    return *(uint32_t*)&h2;
}

// fp32 -> fp16 (vectorized)
__global__ void tof16_kernel(const float* __restrict__ in,
                             __half* __restrict__ o, int n4)
{
    int i = blockIdx.x * blockDim.x + threadIdx.x;
    if (i < n4) {
        float4 v = ((const float4*)in)[i];
        ((uint2*)o)[i] = make_uint2(pack_f16(v.x, v.y), pack_f16(v.z, v.w));
    }
}

// Transpose all 4 weight matrices [K][N] -> [N][K] fp16 in one launch (z=idx).
__global__ void transpose_all_kernel(const float* __restrict__ W0,
                                     const float* __restrict__ W1,
                                     const float* __restrict__ W2,
                                     const float* __restrict__ W3,
                                     __half* __restrict__ o)
{
    __shared__ float t[32][33];
    int z = blockIdx.z;
    const float* W = (z == 0) ? W0 : (z == 1) ? W1 : (z == 2) ? W2 : W3;
    __half* dst = o + (size_t)z * 1024 * 1024;

    int bx = blockIdx.x * 32, by = blockIdx.y * 32;
    int x = bx + threadIdx.x;
#pragma unroll
    for (int j = 0; j < 32; j += 8)
        t[threadIdx.y + j][threadIdx.x] = W[(size_t)(by + threadIdx.y + j) * 1024 + x];
    __syncthreads();
    int k = by + threadIdx.x;
#pragma unroll
    for (int j = 0; j < 32; j += 8) {
        int n = bx + threadIdx.y + j;
        dst[(size_t)n * 1024 + k] = __float2half(t[threadIdx.x][threadIdx.y + j]);
    }
}

// ---------------------------------------------------------------------------
#define WSZc ((size_t)1024*1024)

__device__ __forceinline__ uint32_t sw_off64(int row, int ch) {
    return (uint32_t)(row * 64 + ((ch ^ ((row >> 1) & 3)) << 4));
}

// ---------------------------------------------------------------------------
// Fused QKV projection, 1-pass fp16, tile 128x96 over contiguous B [3072][1024].
// grid (32, 64) = 2048 CTAs -> 6.92 waves at 2 CTA/SM.
// ---------------------------------------------------------------------------
__global__ __launch_bounds__(256, 2) void gemm_qkv_kernel(
    const __half* __restrict__ Ah,
    const __half* __restrict__ Wth,
    const float* __restrict__ bq, const float* __restrict__ bk, const float* __restrict__ bv,
    __half* __restrict__ qo, __half* __restrict__ ko, __half* __restrict__ vo)
{
    __shared__ __align__(1024) char smem[3 * 16384];  /* per stage: A 8KB @0, B 6KB @8192 */

    const int tid = threadIdx.x;
    const int lane = tid & 31;
    const int wid = tid >> 5;
    const int wm = wid & 3;      // 0..3 : 32 m-rows each
    const int wn = wid >> 2;     // 0..1 : 48 n-cols each
    const int m0 = blockIdx.y * 128;
    const int n0 = blockIdx.x * 96;   // global n in [0,3072)
    const uint32_t sb = smem_u32(smem);

    float c[2][6][4];
#pragma unroll
    for (int i = 0; i < 2; i++)
#pragma unroll
        for (int jj = 0; jj < 6; jj++)
#pragma unroll
            for (int q = 0; q < 4; q++) c[i][jj][q] = 0.0f;

    auto issue = [&](int kk) {
        int slot = kk % 3;
        int kp = kk * 32;
        uint32_t dA = sb + (uint32_t)slot * 16384u;
        uint32_t dB = dA + 8192u;
#pragma unroll
        for (int i = 0; i < 2; i++) {
            int id = tid + i * 256;
            int row = id >> 2, ch = id & 3;
            CPASYNC16(dA + sw_off64(row, ch), Ah + (size_t)(m0 + row) * KK + kp + ch * 8);
        }
#pragma unroll
        for (int i = 0; i < 2; i++) {
            int id = tid + i * 256;
            if (id < 384) {
                int row = id >> 2, ch = id & 3;
                CPASYNC16(dB + sw_off64(row, ch),
                          Wth + (size_t)(n0 + row) * KK + kp + ch * 8);
            }
        }
        asm volatile("cp.async.commit_group;" ::: "memory");
    };

    issue(0);
    issue(1);

    for (int kk = 0; kk < 32; kk++) {
        if (kk < 31) asm volatile("cp.async.wait_group 1;" ::: "memory");
        else         asm volatile("cp.async.wait_group 0;" ::: "memory");
        __syncthreads();
        if (kk + 2 < 32) issue(kk + 2);

        uint32_t aBase = sb + (uint32_t)(kk % 3) * 16384u;
        uint32_t bBase = aBase + 8192u;

#pragma unroll
        for (int ks = 0; ks < 2; ks++) {
            uint32_t a[2][4];
#pragma unroll
            for (int mi = 0; mi < 2; mi++) {
                int row = wm * 32 + mi * 16 + (lane & 15);
                int ch = ks * 2 + (lane >> 4);
                LDSM4(a[mi], aBase + sw_off64(row, ch));
            }
            uint32_t b[3][4];
#pragma unroll
            for (int nj = 0; nj < 3; nj++) {
                int row = wn * 48 + nj * 16 + ((lane >> 4) << 3) + (lane & 7);
                int ch = ks * 2 + ((lane >> 3) & 1);
                LDSM4(b[nj], bBase + sw_off64(row, ch));
            }
#pragma unroll
            for (int mi = 0; mi < 2; mi++)
#pragma unroll
                for (int ni = 0; ni < 6; ni++)
                    MMA16816(c[mi][ni], a[mi],
                             b[ni >> 1][(ni & 1) * 2 + 0], b[ni >> 1][(ni & 1) * 2 + 1]);
        }
    }

#pragma unroll
    for (int mi = 0; mi < 2; mi++) {
#pragma unroll
        for (int ni = 0; ni < 6; ni++) {
            int r0 = m0 + wm * 32 + mi * 16 + (lane >> 2);
            int n = n0 + wn * 48 + ni * 8 + (lane & 3) * 2;   // global 0..3071
            int j = n >> 10;
            int nl = n & 1023;
            const float* bias = (j == 0) ? bq : (j == 1) ? bk : bv;
            __half* oh = (j == 0) ? qo : (j == 1) ? ko : vo;
            const float scale = (j == 0) ? QSCALE : 1.0f;
            float2 bvv = *(const float2*)&bias[nl];
#pragma unroll
            for (int rr = 0; rr < 2; rr++) {
                int m = r0 + rr * 8;
                float vx = (c[mi][ni][rr * 2 + 0] + bvv.x) * scale;
                float vy = (c[mi][ni][rr * 2 + 1] + bvv.y) * scale;
                int bb = m >> 11, s = m & (SS - 1);
                int h = nl >> 6, d = nl & 63;
                size_t idx = (((size_t)bb * HH + h) * SS + s) * DKK + d;
                *(uint32_t*)&oh[idx] = pack_f16(vx, vy);
            }
        }
    }
}

// ---------------------------------------------------------------------------
// Output projection GEMM, 1-pass fp16, fp32 out.
// ---------------------------------------------------------------------------
__global__ __launch_bounds__(256, 2) void gemm_out_kernel(
    const __half* __restrict__ Ah, const __half* __restrict__ Bh,
    const float* __restrict__ bias, float* __restrict__ out)
{
    __shared__ __align__(1024) char smem[3 * 16384];

    const int tid = threadIdx.x;
    const int lane = tid & 31;
    const int wid = tid >> 5;
    const int wm = wid & 3;
    const int wn = wid >> 2;
    const int m0 = blockIdx.y * 128;
    const int n0 = blockIdx.x * 128;
    const uint32_t sb = smem_u32(smem);

    float c[2][8][4];
#pragma unroll
    for (int i = 0; i < 2; i++)
#pragma unroll
        for (int jj = 0; jj < 8; jj++)
#pragma unroll
            for (int q = 0; q < 4; q++) c[i][jj][q] = 0.0f;

    auto issue = [&](int kk) {
        int slot = kk % 3;
        int kp = kk * 32;
        uint32_t dA = sb + (uint32_t)slot * 16384u;
        uint32_t dB = dA + 8192u;
#pragma unroll
        for (int i = 0; i < 2; i++) {
            int id = tid + i * 256;
            int row = id >> 2, ch = id & 3;
            uint32_t so = sw_off64(row, ch);
            CPASYNC16(dA + so, Ah + (size_t)(m0 + row) * KK + kp + ch * 8);
            CPASYNC16(dB + so, Bh + (size_t)(n0 + row) * KK + kp + ch * 8);
        }
        asm volatile("cp.async.commit_group;" ::: "memory");
    };

    issue(0);
    issue(1);

    for (int kk = 0; kk < 32; kk++) {
        if (kk < 31) asm volatile("cp.async.wait_group 1;" ::: "memory");
        else         asm volatile("cp.async.wait_group 0;" ::: "memory");
        __syncthreads();
        if (kk + 2 < 32) issue(kk + 2);

        uint32_t aBase = sb + (uint32_t)(kk % 3) * 16384u;
        uint32_t bBase = aBase + 8192u;

#pragma unroll
        for (int ks = 0; ks < 2; ks++) {
            uint32_t a[2][4];
#pragma unroll
            for (int mi = 0; mi < 2; mi++) {
                int row = wm * 32 + mi * 16 + (lane & 15);
                int ch = ks * 2 + (lane >> 4);
                LDSM4(a[mi], aBase + sw_off64(row, ch));
            }
            uint32_t b[4][4];
#pragma unroll
            for (int nj = 0; nj < 4; nj++) {
                int row = wn * 64 + nj * 16 + ((lane >> 4) << 3) + (lane & 7);
                int ch = ks * 2 + ((lane >> 3) & 1);
                LDSM4(b[nj], bBase + sw_off64(row, ch));
            }
#pragma unroll
            for (int mi = 0; mi < 2; mi++)
#pragma unroll
                for (int ni = 0; ni < 8; ni++)
                    MMA16816(c[mi][ni], a[mi],
                             b[ni >> 1][(ni & 1) * 2 + 0], b[ni >> 1][(ni & 1) * 2 + 1]);
        }
    }

#pragma unroll
    for (int mi = 0; mi < 2; mi++) {
#pragma unroll
        for (int ni = 0; ni < 8; ni++) {
            int r0 = m0 + wm * 32 + mi * 16 + (lane >> 2);
            int nc = n0 + wn * 64 + ni * 8 + (lane & 3) * 2;
            float2 bvv = *(const float2*)&bias[nc];
#pragma unroll
            for (int rr = 0; rr < 2; rr++) {
                int m = r0 + rr * 8;
                *(float2*)&out[(size_t)m * NN + nc] =
                    make_float2(c[mi][ni][rr * 2 + 0] + bvv.x,
                                c[mi][ni][rr * 2 + 1] + bvv.y);
            }
        }
    }
}

// ---------------------------------------------------------------------------
// HMMA flash attention, fp16, base-2 softmax (scale folded into Q).
// 128 q-rows/CTA, 64-key tiles, 4-stage pipeline, 80KB smem -> 2 CTA/SM.
// ---------------------------------------------------------------------------
__device__ __forceinline__ uint32_t sw_off128(int row, int ch) {
    return (uint32_t)(row * 128 + ((ch ^ (row & 7)) << 4));
}

#define ATTN_SMEM 81920
#define OFF_Q 0
#define OFF_STG 16384
#define NT (SS/64)

__global__ __launch_bounds__(256, 2) void attn_mma_kernel(
    const __half* __restrict__ Q, const __half* __restrict__ K,
    const __half* __restrict__ V, __half* __restrict__ C)
{
    extern __shared__ __align__(1024) char dsm[];
    const uint32_t sb = smem_u32(dsm);

    const int tid = threadIdx.x;
    const int lane = tid & 31;
    const int wm = tid >> 5;
    const int b = blockIdx.z, h = blockIdx.y;
    const int q0 = blockIdx.x * 128;
    const size_t base = ((size_t)b * HH + h) * SS * DKK;

    {
        uint32_t dq = sb + OFF_Q;
#pragma unroll
        for (int i = 0; i < 4; i++) {
            int id = tid + i * 256;
            int row = id >> 3, ch = id & 7;
            CPASYNC16(dq + sw_off128(row, ch), Q + base + (size_t)(q0 + row) * DKK + ch * 8);
        }
        asm volatile("cp.async.commit_group;" ::: "memory");
    }

    auto issue_kv = [&](int t) {
        uint32_t st = sb + OFF_STG + (uint32_t)(t & 3) * 16384u;
#pragma unroll
        for (int i = 0; i < 2; i++) {
            int id = tid + i * 256;
            int row = id >> 3, ch = id & 7;
            uint32_t so = sw_off128(row, ch);
            CPASYNC16(st + so,         K + base + (size_t)(t * 64 + row) * DKK + ch * 8);
            CPASYNC16(st + 8192u + so, V + base + (size_t)(t * 64 + row) * DKK + ch * 8);
        }
        asm volatile("cp.async.commit_group;" ::: "memory");
    };

    issue_kv(0);
    issue_kv(1);
    issue_kv(2);

    asm volatile("cp.async.wait_group 3;" ::: "memory");
    __syncthreads();

    uint32_t qh[4][4];
#pragma unroll
    for (int ks = 0; ks < 4; ks++) {
        int row = wm * 16 + (lane & 15);
        int ch = ks * 2 + (lane >> 4);
        LDSM4(qh[ks], sb + OFF_Q + sw_off128(row, ch));
    }

    float o[8][4];
#pragma unroll
    for (int i = 0; i < 8; i++)
#pragma unroll
        for (int j = 0; j < 4; j++) o[i][j] = 0.0f;
    float m0 = -1e30f, m1 = -1e30f, l0 = 0.0f, l1 = 0.0f;

    for (int t = 0; t < NT; t++) {
        if (t <= NT - 3)      asm volatile("cp.async.wait_group 2;" ::: "memory");
        else if (t == NT - 2) asm volatile("cp.async.wait_group 1;" ::: "memory");
        else                  asm volatile("cp.async.wait_group 0;" ::: "memory");
        __syncthreads();
        if (t + 3 < NT) issue_kv(t + 3);

        uint32_t st = sb + OFF_STG + (uint32_t)(t & 3) * 16384u;
        uint32_t kh = st, vh = st + 8192u;

        float s[8][4];
#pragma unroll
        for (int i = 0; i < 8; i++)
#pragma unroll
            for (int j = 0; j < 4; j++) s[i][j] = 0.0f;

#pragma unroll
        for (int ks = 0; ks < 4; ks++) {
#pragma unroll
            for (int nj = 0; nj < 4; nj++) {
                int row = nj * 16 + ((lane >> 4) << 3) + (lane & 7);
                int ch = ks * 2 + ((lane >> 3) & 1);
                uint32_t bh[4];
                LDSM4(bh, kh + sw_off128(row, ch));
#pragma unroll
                for (int half = 0; half < 2; half++)
                    MMA16816(s[nj * 2 + half], qh[ks], bh[half * 2], bh[half * 2 + 1]);
            }
        }

        // ---- online softmax (base-2 domain)
        float mt0 = -1e30f, mt1 = -1e30f;
#pragma unroll
        for (int ni = 0; ni < 8; ni++) {
            mt0 = fmaxf(mt0, fmaxf(s[ni][0], s[ni][1]));
            mt1 = fmaxf(mt1, fmaxf(s[ni][2], s[ni][3]));
        }
        mt0 = fmaxf(mt0, __shfl_xor_sync(0xffffffffu, mt0, 1));
        mt0 = fmaxf(mt0, __shfl_xor_sync(0xffffffffu, mt0, 2));
        mt1 = fmaxf(mt1, __shfl_xor_sync(0xffffffffu, mt1, 1));
        mt1 = fmaxf(mt1, __shfl_xor_sync(0xffffffffu, mt1, 2));
        float mn0 = fmaxf(m0, mt0), mn1 = fmaxf(m1, mt1);
        float a0 = exp2f(m0 - mn0), a1 = exp2f(m1 - mn1);
        float ps0 = 0.0f, ps1 = 0.0f;
#pragma unroll
        for (int ni = 0; ni < 8; ni++) {
            s[ni][0] = exp2f(s[ni][0] - mn0);
            s[ni][1] = exp2f(s[ni][1] - mn0);
            s[ni][2] = exp2f(s[ni][2] - mn1);
            s[ni][3] = exp2f(s[ni][3] - mn1);
            ps0 += s[ni][0] + s[ni][1];
            ps1 += s[ni][2] + s[ni][3];
        }
        ps0 += __shfl_xor_sync(0xffffffffu, ps0, 1);
        ps0 += __shfl_xor_sync(0xffffffffu, ps0, 2);
        ps1 += __shfl_xor_sync(0xffffffffu, ps1, 1);
        ps1 += __shfl_xor_sync(0xffffffffu, ps1, 2);
        l0 = l0 * a0 + ps0; l1 = l1 * a1 + ps1;
        m0 = mn0; m1 = mn1;
#pragma unroll
        for (int ni = 0; ni < 8; ni++) {
            o[ni][0] *= a0; o[ni][1] *= a0;
            o[ni][2] *= a1; o[ni][3] *= a1;
        }

        // ---- O += P @ V
#pragma unroll
        for (int kb = 0; kb < 4; kb++) {
            uint32_t ph[4];
            ph[0] = pack_f16(s[2*kb][0],   s[2*kb][1]);
            ph[1] = pack_f16(s[2*kb][2],   s[2*kb][3]);
            ph[2] = pack_f16(s[2*kb+1][0], s[2*kb+1][1]);
            ph[3] = pack_f16(s[2*kb+1][2], s[2*kb+1][3]);
#pragma unroll
            for (int dj = 0; dj < 4; dj++) {
                int qm = lane >> 3;
                int row = kb * 16 + (qm & 1) * 8 + (lane & 7);
                int ch = dj * 2 + (qm >> 1);
                uint32_t vr[4];
                LDSM4T(vr, vh + sw_off128(row, ch));
#pragma unroll
                for (int half = 0; half < 2; half++)
                    MMA16816(o[dj * 2 + half], ph, vr[half * 2], vr[half * 2 + 1]);
            }
        }
    }

    float inv0 = 1.0f / l0, inv1 = 1.0f / l1;
    int srow0 = q0 + wm * 16 + (lane >> 2);
#pragma unroll
    for (int ni = 0; ni < 8; ni++) {
        int d = ni * 8 + (lane & 3) * 2;
        size_t i0 = ((size_t)b * SS + srow0) * NN + h * DKK + d;
        size_t i1 = ((size_t)b * SS + srow0 + 8) * NN + h * DKK + d;
        *(uint32_t*)&C[i0] = pack_f16(o[ni][0] * inv0, o[ni][1] * inv0);
        *(uint32_t*)&C[i1] = pack_f16(o[ni][2] * inv1, o[ni][3] * inv1);
    }
}

// ---------------------------------------------------------------------------
extern "C" void kernel_launch(void* const* d_in, const int* in_sizes, int n_in,
                              void* d_out, int out_size)
{
    const float* x  = (const float*)d_in[0];
    const float* Wq = (const float*)d_in[1];
    const float* bq = (const float*)d_in[2];
    const float* Wk = (const float*)d_in[3];
    const float* bk = (const float*)d_in[4];
    const float* Wv = (const float*)d_in[5];
    const float* bv = (const float*)d_in[6];
    const float* Wo = (const float*)d_in[7];
    const float* bo = (const float*)d_in[8];
    float* out = (float*)d_out;

    __half *q, *k, *v, *xh, *c, *wt;
    cudaGetSymbolAddress((void**)&q, g_q);
    cudaGetSymbolAddress((void**)&k, g_k);
    cudaGetSymbolAddress((void**)&v, g_v);
    cudaGetSymbolAddress((void**)&xh, g_x);
    cudaGetSymbolAddress((void**)&c, g_c);
    cudaGetSymbolAddress((void**)&wt, g_wt);

    cudaFuncSetAttribute(attn_mma_kernel, cudaFuncAttributeMaxDynamicSharedMemorySize, ATTN_SMEM);

    tof16_kernel<<<(MM * KK / 4 + 255) / 256, 256>>>(x, xh, MM * KK / 4);

    transpose_all_kernel<<<dim3(32, 32, 4), dim3(32, 8)>>>(Wq, Wk, Wv, Wo, wt);

    gemm_qkv_kernel<<<dim3(32, 64), 256>>>(xh, wt, bq, bk, bv, q, k, v);

    attn_mma_kernel<<<dim3(SS / 128, HH, BB), 256, ATTN_SMEM>>>(q, k, v, c);

    gemm_out_kernel<<<dim3(8, 64), 256>>>(c, wt + 3 * WSZc, bo, out);
}

// round 9
// speedup vs baseline: 12.0575x; 1.0440x over previous
#include <cuda_runtime.h>
#include <cuda_fp16.h>
#include <cstdint>
#include <math.h>

#define BB 4
#define SS 2048
#define EE 1024
#define HH 16
#define DKK 64
#define MM (BB*SS)      /* 8192 */
#define NN (HH*DKK)     /* 1024 */
#define KK EE           /* 1024 */

/* Q scale folded with log2(e): softmax computed in base-2 domain. */
#define QSCALE 0.18033688f   /* 0.125 * 1.44269504 */

// ---------------------------------------------------------------------------
// Scratch (device globals — no allocation allowed)
// ---------------------------------------------------------------------------
__device__ __half g_q[(size_t)MM*NN];
__device__ __half g_k[(size_t)MM*NN];
__device__ __half g_v[(size_t)MM*NN];
__device__ __half g_x[(size_t)MM*KK];
__device__ __half g_c[(size_t)MM*NN];
__device__ __half g_wt[(size_t)4*1024*1024];

// ---------------------------------------------------------------------------
__device__ __forceinline__ uint32_t smem_u32(const void* p) {
    uint32_t a;
    asm("{ .reg .u64 t; cvta.to.shared.u64 t, %1; cvt.u32.u64 %0, t; }"
        : "=r"(a) : "l"(p));
    return a;
}

__device__ __forceinline__ float ex2(float x) {
    float y;
    asm("ex2.approx.ftz.f32 %0, %1;" : "=f"(y) : "f"(x));
    return y;
}

#define MMA16816(C, A, B0, B1) \
    asm volatile("mma.sync.aligned.m16n8k16.row.col.f32.f16.f16.f32 " \
                 "{%0,%1,%2,%3}, {%4,%5,%6,%7}, {%8,%9}, {%0,%1,%2,%3};" \
                 : "+f"((C)[0]), "+f"((C)[1]), "+f"((C)[2]), "+f"((C)[3]) \
                 : "r"((A)[0]), "r"((A)[1]), "r"((A)[2]), "r"((A)[3]), \
                   "r"(B0), "r"(B1))

#define LDSM4(R, addr) \
    asm volatile("ldmatrix.sync.aligned.m8n8.x4.shared.b16 {%0,%1,%2,%3}, [%4];" \
                 : "=r"((R)[0]), "=r"((R)[1]), "=r"((R)[2]), "=r"((R)[3]) : "r"(addr))

#define LDSM4T(R, addr) \
    asm volatile("ldmatrix.sync.aligned.m8n8.x4.trans.shared.b16 {%0,%1,%2,%3}, [%4];" \
                 : "=r"((R)[0]), "=r"((R)[1]), "=r"((R)[2]), "=r"((R)[3]) : "r"(addr))

#define CPASYNC16(dst, src) \
    asm volatile("cp.async.cg.shared.global [%0], [%1], 16;" :: "r"(dst), "l"(src) : "memory")

__device__ __forceinline__ uint32_t pack_f16(float x, float y) {
    __half2 h2 = __floats2half2_rn(x, y);
    return *(uint32_t*)&h2;
}

// fp32 -> fp16 (vectorized)
__global__ void tof16_kernel(const float* __restrict__ in,
                             __half* __restrict__ o, int n4)
{
    int i = blockIdx.x * blockDim.x + threadIdx.x;
    if (i < n4) {
        float4 v = ((const float4*)in)[i];
        ((uint2*)o)[i] = make_uint2(pack_f16(v.x, v.y), pack_f16(v.z, v.w));
    }
}

// Transpose all 4 weight matrices [K][N] -> [N][K] fp16 in one launch (z=idx).
__global__ void transpose_all_kernel(const float* __restrict__ W0,
                                     const float* __restrict__ W1,
                                     const float* __restrict__ W2,
                                     const float* __restrict__ W3,
                                     __half* __restrict__ o)
{
    __shared__ float t[32][33];
    int z = blockIdx.z;
    const float* W = (z == 0) ? W0 : (z == 1) ? W1 : (z == 2) ? W2 : W3;
    __half* dst = o + (size_t)z * 1024 * 1024;

    int bx = blockIdx.x * 32, by = blockIdx.y * 32;
    int x = bx + threadIdx.x;
#pragma unroll
    for (int j = 0; j < 32; j += 8)
        t[threadIdx.y + j][threadIdx.x] = W[(size_t)(by + threadIdx.y + j) * 1024 + x];
    __syncthreads();
    int k = by + threadIdx.x;
#pragma unroll
    for (int j = 0; j < 32; j += 8) {
        int n = bx + threadIdx.y + j;
        dst[(size_t)n * 1024 + k] = __float2half(t[threadIdx.x][threadIdx.y + j]);
    }
}

// ---------------------------------------------------------------------------
#define WSZc ((size_t)1024*1024)

__device__ __forceinline__ uint32_t sw_off64(int row, int ch) {
    return (uint32_t)(row * 64 + ((ch ^ ((row >> 1) & 3)) << 4));
}

// ---------------------------------------------------------------------------
// Fused QKV projection, 1-pass fp16, tile 128x96 over contiguous B [3072][1024].
// ---------------------------------------------------------------------------
__global__ __launch_bounds__(256, 2) void gemm_qkv_kernel(
    const __half* __restrict__ Ah,
    const __half* __restrict__ Wth,
    const float* __restrict__ bq, const float* __restrict__ bk, const float* __restrict__ bv,
    __half* __restrict__ qo, __half* __restrict__ ko, __half* __restrict__ vo)
{
    __shared__ __align__(1024) char smem[3 * 16384];

    const int tid = threadIdx.x;
    const int lane = tid & 31;
    const int wid = tid >> 5;
    const int wm = wid & 3;
    const int wn = wid >> 2;
    const int m0 = blockIdx.y * 128;
    const int n0 = blockIdx.x * 96;
    const uint32_t sb = smem_u32(smem);

    float c[2][6][4];
#pragma unroll
    for (int i = 0; i < 2; i++)
#pragma unroll
        for (int jj = 0; jj < 6; jj++)
#pragma unroll
            for (int q = 0; q < 4; q++) c[i][jj][q] = 0.0f;

    auto issue = [&](int kk) {
        int slot = kk % 3;
        int kp = kk * 32;
        uint32_t dA = sb + (uint32_t)slot * 16384u;
        uint32_t dB = dA + 8192u;
#pragma unroll
        for (int i = 0; i < 2; i++) {
            int id = tid + i * 256;
            int row = id >> 2, ch = id & 3;
            CPASYNC16(dA + sw_off64(row, ch), Ah + (size_t)(m0 + row) * KK + kp + ch * 8);
        }
#pragma unroll
        for (int i = 0; i < 2; i++) {
            int id = tid + i * 256;
            if (id < 384) {
                int row = id >> 2, ch = id & 3;
                CPASYNC16(dB + sw_off64(row, ch),
                          Wth + (size_t)(n0 + row) * KK + kp + ch * 8);
            }
        }
        asm volatile("cp.async.commit_group;" ::: "memory");
    };

    issue(0);
    issue(1);

    for (int kk = 0; kk < 32; kk++) {
        if (kk < 31) asm volatile("cp.async.wait_group 1;" ::: "memory");
        else         asm volatile("cp.async.wait_group 0;" ::: "memory");
        __syncthreads();
        if (kk + 2 < 32) issue(kk + 2);

        uint32_t aBase = sb + (uint32_t)(kk % 3) * 16384u;
        uint32_t bBase = aBase + 8192u;

#pragma unroll
        for (int ks = 0; ks < 2; ks++) {
            uint32_t a[2][4];
#pragma unroll
            for (int mi = 0; mi < 2; mi++) {
                int row = wm * 32 + mi * 16 + (lane & 15);
                int ch = ks * 2 + (lane >> 4);
                LDSM4(a[mi], aBase + sw_off64(row, ch));
            }
            uint32_t b[3][4];
#pragma unroll
            for (int nj = 0; nj < 3; nj++) {
                int row = wn * 48 + nj * 16 + ((lane >> 4) << 3) + (lane & 7);
                int ch = ks * 2 + ((lane >> 3) & 1);
                LDSM4(b[nj], bBase + sw_off64(row, ch));
            }
#pragma unroll
            for (int mi = 0; mi < 2; mi++)
#pragma unroll
                for (int ni = 0; ni < 6; ni++)
                    MMA16816(c[mi][ni], a[mi],
                             b[ni >> 1][(ni & 1) * 2 + 0], b[ni >> 1][(ni & 1) * 2 + 1]);
        }
    }

#pragma unroll
    for (int mi = 0; mi < 2; mi++) {
#pragma unroll
        for (int ni = 0; ni < 6; ni++) {
            int r0 = m0 + wm * 32 + mi * 16 + (lane >> 2);
            int n = n0 + wn * 48 + ni * 8 + (lane & 3) * 2;
            int j = n >> 10;
            int nl = n & 1023;
            const float* bias = (j == 0) ? bq : (j == 1) ? bk : bv;
            __half* oh = (j == 0) ? qo : (j == 1) ? ko : vo;
            const float scale = (j == 0) ? QSCALE : 1.0f;
            float2 bvv = *(const float2*)&bias[nl];
#pragma unroll
            for (int rr = 0; rr < 2; rr++) {
                int m = r0 + rr * 8;
                float vx = (c[mi][ni][rr * 2 + 0] + bvv.x) * scale;
                float vy = (c[mi][ni][rr * 2 + 1] + bvv.y) * scale;
                int bb = m >> 11, s = m & (SS - 1);
                int h = nl >> 6, d = nl & 63;
                size_t idx = (((size_t)bb * HH + h) * SS + s) * DKK + d;
                *(uint32_t*)&oh[idx] = pack_f16(vx, vy);
            }
        }
    }
}

// ---------------------------------------------------------------------------
// Output projection GEMM, 1-pass fp16, fp32 out.
// ---------------------------------------------------------------------------
__global__ __launch_bounds__(256, 2) void gemm_out_kernel(
    const __half* __restrict__ Ah, const __half* __restrict__ Bh,
    const float* __restrict__ bias, float* __restrict__ out)
{
    __shared__ __align__(1024) char smem[3 * 16384];

    const int tid = threadIdx.x;
    const int lane = tid & 31;
    const int wid = tid >> 5;
    const int wm = wid & 3;
    const int wn = wid >> 2;
    const int m0 = blockIdx.y * 128;
    const int n0 = blockIdx.x * 128;
    const uint32_t sb = smem_u32(smem);

    float c[2][8][4];
#pragma unroll
    for (int i = 0; i < 2; i++)
#pragma unroll
        for (int jj = 0; jj < 8; jj++)
#pragma unroll
            for (int q = 0; q < 4; q++) c[i][jj][q] = 0.0f;

    auto issue = [&](int kk) {
        int slot = kk % 3;
        int kp = kk * 32;
        uint32_t dA = sb + (uint32_t)slot * 16384u;
        uint32_t dB = dA + 8192u;
#pragma unroll
        for (int i = 0; i < 2; i++) {
            int id = tid + i * 256;
            int row = id >> 2, ch = id & 3;
            uint32_t so = sw_off64(row, ch);
            CPASYNC16(dA + so, Ah + (size_t)(m0 + row) * KK + kp + ch * 8);
            CPASYNC16(dB + so, Bh + (size_t)(n0 + row) * KK + kp + ch * 8);
        }
        asm volatile("cp.async.commit_group;" ::: "memory");
    };

    issue(0);
    issue(1);

    for (int kk = 0; kk < 32; kk++) {
        if (kk < 31) asm volatile("cp.async.wait_group 1;" ::: "memory");
        else         asm volatile("cp.async.wait_group 0;" ::: "memory");
        __syncthreads();
        if (kk + 2 < 32) issue(kk + 2);

        uint32_t aBase = sb + (uint32_t)(kk % 3) * 16384u;
        uint32_t bBase = aBase + 8192u;

#pragma unroll
        for (int ks = 0; ks < 2; ks++) {
            uint32_t a[2][4];
#pragma unroll
            for (int mi = 0; mi < 2; mi++) {
                int row = wm * 32 + mi * 16 + (lane & 15);
                int ch = ks * 2 + (lane >> 4);
                LDSM4(a[mi], aBase + sw_off64(row, ch));
            }
            uint32_t b[4][4];
#pragma unroll
            for (int nj = 0; nj < 4; nj++) {
                int row = wn * 64 + nj * 16 + ((lane >> 4) << 3) + (lane & 7);
                int ch = ks * 2 + ((lane >> 3) & 1);
                LDSM4(b[nj], bBase + sw_off64(row, ch));
            }
#pragma unroll
            for (int mi = 0; mi < 2; mi++)
#pragma unroll
                for (int ni = 0; ni < 8; ni++)
                    MMA16816(c[mi][ni], a[mi],
                             b[ni >> 1][(ni & 1) * 2 + 0], b[ni >> 1][(ni & 1) * 2 + 1]);
        }
    }

#pragma unroll
    for (int mi = 0; mi < 2; mi++) {
#pragma unroll
        for (int ni = 0; ni < 8; ni++) {
            int r0 = m0 + wm * 32 + mi * 16 + (lane >> 2);
            int nc = n0 + wn * 64 + ni * 8 + (lane & 3) * 2;
            float2 bvv = *(const float2*)&bias[nc];
#pragma unroll
            for (int rr = 0; rr < 2; rr++) {
                int m = r0 + rr * 8;
                *(float2*)&out[(size_t)m * NN + nc] =
                    make_float2(c[mi][ni][rr * 2 + 0] + bvv.x,
                                c[mi][ni][rr * 2 + 1] + bvv.y);
            }
        }
    }
}

// ---------------------------------------------------------------------------
// HMMA flash attention, fp16, base-2 softmax, tensor-core row sums.
// 128 q-rows/CTA, 64-key tiles, 4-stage pipeline, 80KB smem -> 2 CTA/SM.
// ---------------------------------------------------------------------------
__device__ __forceinline__ uint32_t sw_off128(int row, int ch) {
    return (uint32_t)(row * 128 + ((ch ^ (row & 7)) << 4));
}

#define ATTN_SMEM 81920
#define OFF_Q 0
#define OFF_STG 16384
#define NT (SS/64)

__global__ __launch_bounds__(256, 2) void attn_mma_kernel(
    const __half* __restrict__ Q, const __half* __restrict__ K,
    const __half* __restrict__ V, __half* __restrict__ C)
{
    extern __shared__ __align__(1024) char dsm[];
    const uint32_t sb = smem_u32(dsm);

    const int tid = threadIdx.x;
    const int lane = tid & 31;
    const int wm = tid >> 5;
    const int b = blockIdx.z, h = blockIdx.y;
    const int q0 = blockIdx.x * 128;
    const size_t base = ((size_t)b * HH + h) * SS * DKK;

    /* constant B-fragment of a virtual ones-column (n=0 of an 8-col block):
       m16n8k16 B frag: thread t holds col n = t/4 -> lanes 0..3 own n=0. */
    const uint32_t bone = (lane < 4) ? 0x3C003C00u : 0u;

    {
        uint32_t dq = sb + OFF_Q;
#pragma unroll
        for (int i = 0; i < 4; i++) {
            int id = tid + i * 256;
            int row = id >> 3, ch = id & 7;
            CPASYNC16(dq + sw_off128(row, ch), Q + base + (size_t)(q0 + row) * DKK + ch * 8);
        }
        asm volatile("cp.async.commit_group;" ::: "memory");
    }

    auto issue_kv = [&](int t) {
        uint32_t st = sb + OFF_STG + (uint32_t)(t & 3) * 16384u;
#pragma unroll
        for (int i = 0; i < 2; i++) {
            int id = tid + i * 256;
            int row = id >> 3, ch = id & 7;
            uint32_t so = sw_off128(row, ch);
            CPASYNC16(st + so,         K + base + (size_t)(t * 64 + row) * DKK + ch * 8);
            CPASYNC16(st + 8192u + so, V + base + (size_t)(t * 64 + row) * DKK + ch * 8);
        }
        asm volatile("cp.async.commit_group;" ::: "memory");
    };

    issue_kv(0);
    issue_kv(1);
    issue_kv(2);

    asm volatile("cp.async.wait_group 3;" ::: "memory");
    __syncthreads();

    uint32_t qh[4][4];
#pragma unroll
    for (int ks = 0; ks < 4; ks++) {
        int row = wm * 16 + (lane & 15);
        int ch = ks * 2 + (lane >> 4);
        LDSM4(qh[ks], sb + OFF_Q + sw_off128(row, ch));
    }

    float o[8][4];
#pragma unroll
    for (int i = 0; i < 8; i++)
#pragma unroll
        for (int j = 0; j < 4; j++) o[i][j] = 0.0f;
    float oE[4] = {0.f, 0.f, 0.f, 0.f};   /* l accumulator (ones-column) */
    float m0 = -1e30f, m1 = -1e30f;

    for (int t = 0; t < NT; t++) {
        if (t <= NT - 3)      asm volatile("cp.async.wait_group 2;" ::: "memory");
        else if (t == NT - 2) asm volatile("cp.async.wait_group 1;" ::: "memory");
        else                  asm volatile("cp.async.wait_group 0;" ::: "memory");
        __syncthreads();
        if (t + 3 < NT) issue_kv(t + 3);

        uint32_t st = sb + OFF_STG + (uint32_t)(t & 3) * 16384u;
        uint32_t kh = st, vh = st + 8192u;

        float s[8][4];
#pragma unroll
        for (int i = 0; i < 8; i++)
#pragma unroll
            for (int j = 0; j < 4; j++) s[i][j] = 0.0f;

#pragma unroll
        for (int ks = 0; ks < 4; ks++) {
#pragma unroll
            for (int nj = 0; nj < 4; nj++) {
                int row = nj * 16 + ((lane >> 4) << 3) + (lane & 7);
                int ch = ks * 2 + ((lane >> 3) & 1);
                uint32_t bh[4];
                LDSM4(bh, kh + sw_off128(row, ch));
#pragma unroll
                for (int half = 0; half < 2; half++)
                    MMA16816(s[nj * 2 + half], qh[ks], bh[half * 2], bh[half * 2 + 1]);
            }
        }

        // ---- online softmax (base-2, sums via tensor core)
        float mt0 = -1e30f, mt1 = -1e30f;
#pragma unroll
        for (int ni = 0; ni < 8; ni++) {
            mt0 = fmaxf(mt0, fmaxf(s[ni][0], s[ni][1]));
            mt1 = fmaxf(mt1, fmaxf(s[ni][2], s[ni][3]));
        }
        mt0 = fmaxf(mt0, __shfl_xor_sync(0xffffffffu, mt0, 1));
        mt0 = fmaxf(mt0, __shfl_xor_sync(0xffffffffu, mt0, 2));
        mt1 = fmaxf(mt1, __shfl_xor_sync(0xffffffffu, mt1, 1));
        mt1 = fmaxf(mt1, __shfl_xor_sync(0xffffffffu, mt1, 2));
        float mn0 = fmaxf(m0, mt0), mn1 = fmaxf(m1, mt1);
        float a0 = ex2(m0 - mn0), a1 = ex2(m1 - mn1);
#pragma unroll
        for (int ni = 0; ni < 8; ni++) {
            s[ni][0] = ex2(s[ni][0] - mn0);
            s[ni][1] = ex2(s[ni][1] - mn0);
            s[ni][2] = ex2(s[ni][2] - mn1);
            s[ni][3] = ex2(s[ni][3] - mn1);
        }
        m0 = mn0; m1 = mn1;
#pragma unroll
        for (int ni = 0; ni < 8; ni++) {
            o[ni][0] *= a0; o[ni][1] *= a0;
            o[ni][2] *= a1; o[ni][3] *= a1;
        }
        oE[0] *= a0; oE[1] *= a0; oE[2] *= a1; oE[3] *= a1;

        // ---- O += P @ V ; l += P @ ones
#pragma unroll
        for (int kb = 0; kb < 4; kb++) {
            uint32_t ph[4];
            ph[0] = pack_f16(s[2*kb][0],   s[2*kb][1]);
            ph[1] = pack_f16(s[2*kb][2],   s[2*kb][3]);
            ph[2] = pack_f16(s[2*kb+1][0], s[2*kb+1][1]);
            ph[3] = pack_f16(s[2*kb+1][2], s[2*kb+1][3]);
            MMA16816(oE, ph, bone, bone);
#pragma unroll
            for (int dj = 0; dj < 4; dj++) {
                int qm = lane >> 3;
                int row = kb * 16 + (qm & 1) * 8 + (lane & 7);
                int ch = dj * 2 + (qm >> 1);
                uint32_t vr[4];
                LDSM4T(vr, vh + sw_off128(row, ch));
#pragma unroll
                for (int half = 0; half < 2; half++)
                    MMA16816(o[dj * 2 + half], ph, vr[half * 2], vr[half * 2 + 1]);
            }
        }
    }

    /* l lives in col 0 of the oE fragment -> lanes with lane%4==0 */
    float l0 = __shfl_sync(0xffffffffu, oE[0], lane & ~3);
    float l1 = __shfl_sync(0xffffffffu, oE[2], lane & ~3);
    float inv0 = 1.0f / l0, inv1 = 1.0f / l1;
    int srow0 = q0 + wm * 16 + (lane >> 2);
#pragma unroll
    for (int ni = 0; ni < 8; ni++) {
        int d = ni * 8 + (lane & 3) * 2;
        size_t i0 = ((size_t)b * SS + srow0) * NN + h * DKK + d;
        size_t i1 = ((size_t)b * SS + srow0 + 8) * NN + h * DKK + d;
        *(uint32_t*)&C[i0] = pack_f16(o[ni][0] * inv0, o[ni][1] * inv0);
        *(uint32_t*)&C[i1] = pack_f16(o[ni][2] * inv1, o[ni][3] * inv1);
    }
}

// ---------------------------------------------------------------------------
extern "C" void kernel_launch(void* const* d_in, const int* in_sizes, int n_in,
                              void* d_out, int out_size)
{
    const float* x  = (const float*)d_in[0];
    const float* Wq = (const float*)d_in[1];
    const float* bq = (const float*)d_in[2];
    const float* Wk = (const float*)d_in[3];
    const float* bk = (const float*)d_in[4];
    const float* Wv = (const float*)d_in[5];
    const float* bv = (const float*)d_in[6];
    const float* Wo = (const float*)d_in[7];
    const float* bo = (const float*)d_in[8];
    float* out = (float*)d_out;

    __half *q, *k, *v, *xh, *c, *wt;
    cudaGetSymbolAddress((void**)&q, g_q);
    cudaGetSymbolAddress((void**)&k, g_k);
    cudaGetSymbolAddress((void**)&v, g_v);
    cudaGetSymbolAddress((void**)&xh, g_x);
    cudaGetSymbolAddress((void**)&c, g_c);
    cudaGetSymbolAddress((void**)&wt, g_wt);

    cudaFuncSetAttribute(attn_mma_kernel, cudaFuncAttributeMaxDynamicSharedMemorySize, ATTN_SMEM);

    tof16_kernel<<<(MM * KK / 4 + 255) / 256, 256>>>(x, xh, MM * KK / 4);

    transpose_all_kernel<<<dim3(32, 32, 4), dim3(32, 8)>>>(Wq, Wk, Wv, Wo, wt);

    gemm_qkv_kernel<<<dim3(32, 64), 256>>>(xh, wt, bq, bk, bv, q, k, v);

    attn_mma_kernel<<<dim3(SS / 128, HH, BB), 256, ATTN_SMEM>>>(q, k, v, c);

    gemm_out_kernel<<<dim3(8, 64), 256>>>(c, wt + 3 * WSZc, bo, out);
}

// round 10
// speedup vs baseline: 12.0862x; 1.0024x over previous
#include <cuda_runtime.h>
#include <cuda_fp16.h>
#include <cstdint>
#include <math.h>

#define BB 4
#define SS 2048
#define EE 1024
#define HH 16
#define DKK 64
#define MM (BB*SS)      /* 8192 */
#define NN (HH*DKK)     /* 1024 */
#define KK EE           /* 1024 */

/* Q scale folded with log2(e): softmax computed in base-2 domain. */
#define QSCALE 0.18033688f   /* 0.125 * 1.44269504 */

// ---------------------------------------------------------------------------
// Scratch (device globals — no allocation allowed)
// ---------------------------------------------------------------------------
__device__ __half g_q[(size_t)MM*NN];
__device__ __half g_k[(size_t)MM*NN];
__device__ __half g_v[(size_t)MM*NN];
__device__ __half g_x[(size_t)MM*KK];
__device__ __half g_c[(size_t)MM*NN];
__device__ __half g_wt[(size_t)4*1024*1024];

// ---------------------------------------------------------------------------
__device__ __forceinline__ uint32_t smem_u32(const void* p) {
    uint32_t a;
    asm("{ .reg .u64 t; cvta.to.shared.u64 t, %1; cvt.u32.u64 %0, t; }"
        : "=r"(a) : "l"(p));
    return a;
}

__device__ __forceinline__ float ex2(float x) {
    float y;
    asm("ex2.approx.ftz.f32 %0, %1;" : "=f"(y) : "f"(x));
    return y;
}

#define MMA16816(C, A, B0, B1) \
    asm volatile("mma.sync.aligned.m16n8k16.row.col.f32.f16.f16.f32 " \
                 "{%0,%1,%2,%3}, {%4,%5,%6,%7}, {%8,%9}, {%0,%1,%2,%3};" \
                 : "+f"((C)[0]), "+f"((C)[1]), "+f"((C)[2]), "+f"((C)[3]) \
                 : "r"((A)[0]), "r"((A)[1]), "r"((A)[2]), "r"((A)[3]), \
                   "r"(B0), "r"(B1))

#define LDSM4(R, addr) \
    asm volatile("ldmatrix.sync.aligned.m8n8.x4.shared.b16 {%0,%1,%2,%3}, [%4];" \
                 : "=r"((R)[0]), "=r"((R)[1]), "=r"((R)[2]), "=r"((R)[3]) : "r"(addr))

#define LDSM4T(R, addr) \
    asm volatile("ldmatrix.sync.aligned.m8n8.x4.trans.shared.b16 {%0,%1,%2,%3}, [%4];" \
                 : "=r"((R)[0]), "=r"((R)[1]), "=r"((R)[2]), "=r"((R)[3]) : "r"(addr))

#define CPASYNC16(dst, src) \
    asm volatile("cp.async.cg.shared.global [%0], [%1], 16;" :: "r"(dst), "l"(src) : "memory")

__device__ __forceinline__ uint32_t pack_f16(float x, float y) {
    __half2 h2 = __floats2half2_rn(x, y);
    return *(uint32_t*)&h2;
}

// fp32 -> fp16 (vectorized)
__global__ void tof16_kernel(const float* __restrict__ in,
                             __half* __restrict__ o, int n4)
{
    int i = blockIdx.x * blockDim.x + threadIdx.x;
    if (i < n4) {
        float4 v = ((const float4*)in)[i];
        ((uint2*)o)[i] = make_uint2(pack_f16(v.x, v.y), pack_f16(v.z, v.w));
    }
}

// Transpose all 4 weight matrices [K][N] -> [N][K] fp16 in one launch (z=idx).
__global__ void transpose_all_kernel(const float* __restrict__ W0,
                                     const float* __restrict__ W1,
                                     const float* __restrict__ W2,
                                     const float* __restrict__ W3,
                                     __half* __restrict__ o)
{
    __shared__ float t[32][33];
    int z = blockIdx.z;
    const float* W = (z == 0) ? W0 : (z == 1) ? W1 : (z == 2) ? W2 : W3;
    __half* dst = o + (size_t)z * 1024 * 1024;

    int bx = blockIdx.x * 32, by = blockIdx.y * 32;
    int x = bx + threadIdx.x;
#pragma unroll
    for (int j = 0; j < 32; j += 8)
        t[threadIdx.y + j][threadIdx.x] = W[(size_t)(by + threadIdx.y + j) * 1024 + x];
    __syncthreads();
    int k = by + threadIdx.x;
#pragma unroll
    for (int j = 0; j < 32; j += 8) {
        int n = bx + threadIdx.y + j;
        dst[(size_t)n * 1024 + k] = __float2half(t[threadIdx.x][threadIdx.y + j]);
    }
}

// ---------------------------------------------------------------------------
#define WSZc ((size_t)1024*1024)

__device__ __forceinline__ uint32_t sw_off64(int row, int ch) {
    return (uint32_t)(row * 64 + ((ch ^ ((row >> 1) & 3)) << 4));
}

// ---------------------------------------------------------------------------
// Fused QKV projection, 1-pass fp16, tile 128x96 over contiguous B [3072][1024].
// ---------------------------------------------------------------------------
__global__ __launch_bounds__(256, 2) void gemm_qkv_kernel(
    const __half* __restrict__ Ah,
    const __half* __restrict__ Wth,
    const float* __restrict__ bq, const float* __restrict__ bk, const float* __restrict__ bv,
    __half* __restrict__ qo, __half* __restrict__ ko, __half* __restrict__ vo)
{
    __shared__ __align__(1024) char smem[3 * 16384];

    const int tid = threadIdx.x;
    const int lane = tid & 31;
    const int wid = tid >> 5;
    const int wm = wid & 3;
    const int wn = wid >> 2;
    const int m0 = blockIdx.y * 128;
    const int n0 = blockIdx.x * 96;
    const uint32_t sb = smem_u32(smem);

    float c[2][6][4];
#pragma unroll
    for (int i = 0; i < 2; i++)
#pragma unroll
        for (int jj = 0; jj < 6; jj++)
#pragma unroll
            for (int q = 0; q < 4; q++) c[i][jj][q] = 0.0f;

    auto issue = [&](int kk) {
        int slot = kk % 3;
        int kp = kk * 32;
        uint32_t dA = sb + (uint32_t)slot * 16384u;
        uint32_t dB = dA + 8192u;
#pragma unroll
        for (int i = 0; i < 2; i++) {
            int id = tid + i * 256;
            int row = id >> 2, ch = id & 3;
            CPASYNC16(dA + sw_off64(row, ch), Ah + (size_t)(m0 + row) * KK + kp + ch * 8);
        }
#pragma unroll
        for (int i = 0; i < 2; i++) {
            int id = tid + i * 256;
            if (id < 384) {
                int row = id >> 2, ch = id & 3;
                CPASYNC16(dB + sw_off64(row, ch),
                          Wth + (size_t)(n0 + row) * KK + kp + ch * 8);
            }
        }
        asm volatile("cp.async.commit_group;" ::: "memory");
    };

    issue(0);
    issue(1);

    for (int kk = 0; kk < 32; kk++) {
        if (kk < 31) asm volatile("cp.async.wait_group 1;" ::: "memory");
        else         asm volatile("cp.async.wait_group 0;" ::: "memory");
        __syncthreads();
        if (kk + 2 < 32) issue(kk + 2);

        uint32_t aBase = sb + (uint32_t)(kk % 3) * 16384u;
        uint32_t bBase = aBase + 8192u;

#pragma unroll
        for (int ks = 0; ks < 2; ks++) {
            uint32_t a[2][4];
#pragma unroll
            for (int mi = 0; mi < 2; mi++) {
                int row = wm * 32 + mi * 16 + (lane & 15);
                int ch = ks * 2 + (lane >> 4);
                LDSM4(a[mi], aBase + sw_off64(row, ch));
            }
            uint32_t b[3][4];
#pragma unroll
            for (int nj = 0; nj < 3; nj++) {
                int row = wn * 48 + nj * 16 + ((lane >> 4) << 3) + (lane & 7);
                int ch = ks * 2 + ((lane >> 3) & 1);
                LDSM4(b[nj], bBase + sw_off64(row, ch));
            }
#pragma unroll
            for (int mi = 0; mi < 2; mi++)
#pragma unroll
                for (int ni = 0; ni < 6; ni++)
                    MMA16816(c[mi][ni], a[mi],
                             b[ni >> 1][(ni & 1) * 2 + 0], b[ni >> 1][(ni & 1) * 2 + 1]);
        }
    }

#pragma unroll
    for (int mi = 0; mi < 2; mi++) {
#pragma unroll
        for (int ni = 0; ni < 6; ni++) {
            int r0 = m0 + wm * 32 + mi * 16 + (lane >> 2);
            int n = n0 + wn * 48 + ni * 8 + (lane & 3) * 2;
            int j = n >> 10;
            int nl = n & 1023;
            const float* bias = (j == 0) ? bq : (j == 1) ? bk : bv;
            __half* oh = (j == 0) ? qo : (j == 1) ? ko : vo;
            const float scale = (j == 0) ? QSCALE : 1.0f;
            float2 bvv = *(const float2*)&bias[nl];
#pragma unroll
            for (int rr = 0; rr < 2; rr++) {
                int m = r0 + rr * 8;
                float vx = (c[mi][ni][rr * 2 + 0] + bvv.x) * scale;
                float vy = (c[mi][ni][rr * 2 + 1] + bvv.y) * scale;
                int bb = m >> 11, s = m & (SS - 1);
                int h = nl >> 6, d = nl & 63;
                size_t idx = (((size_t)bb * HH + h) * SS + s) * DKK + d;
                *(uint32_t*)&oh[idx] = pack_f16(vx, vy);
            }
        }
    }
}

// ---------------------------------------------------------------------------
// Output projection GEMM, 1-pass fp16, fp32 out.
// ---------------------------------------------------------------------------
__global__ __launch_bounds__(256, 2) void gemm_out_kernel(
    const __half* __restrict__ Ah, const __half* __restrict__ Bh,
    const float* __restrict__ bias, float* __restrict__ out)
{
    __shared__ __align__(1024) char smem[3 * 16384];

    const int tid = threadIdx.x;
    const int lane = tid & 31;
    const int wid = tid >> 5;
    const int wm = wid & 3;
    const int wn = wid >> 2;
    const int m0 = blockIdx.y * 128;
    const int n0 = blockIdx.x * 128;
    const uint32_t sb = smem_u32(smem);

    float c[2][8][4];
#pragma unroll
    for (int i = 0; i < 2; i++)
#pragma unroll
        for (int jj = 0; jj < 8; jj++)
#pragma unroll
            for (int q = 0; q < 4; q++) c[i][jj][q] = 0.0f;

    auto issue = [&](int kk) {
        int slot = kk % 3;
        int kp = kk * 32;
        uint32_t dA = sb + (uint32_t)slot * 16384u;
        uint32_t dB = dA + 8192u;
#pragma unroll
        for (int i = 0; i < 2; i++) {
            int id = tid + i * 256;
            int row = id >> 2, ch = id & 3;
            uint32_t so = sw_off64(row, ch);
            CPASYNC16(dA + so, Ah + (size_t)(m0 + row) * KK + kp + ch * 8);
            CPASYNC16(dB + so, Bh + (size_t)(n0 + row) * KK + kp + ch * 8);
        }
        asm volatile("cp.async.commit_group;" ::: "memory");
    };

    issue(0);
    issue(1);

    for (int kk = 0; kk < 32; kk++) {
        if (kk < 31) asm volatile("cp.async.wait_group 1;" ::: "memory");
        else         asm volatile("cp.async.wait_group 0;" ::: "memory");
        __syncthreads();
        if (kk + 2 < 32) issue(kk + 2);

        uint32_t aBase = sb + (uint32_t)(kk % 3) * 16384u;
        uint32_t bBase = aBase + 8192u;

#pragma unroll
        for (int ks = 0; ks < 2; ks++) {
            uint32_t a[2][4];
#pragma unroll
            for (int mi = 0; mi < 2; mi++) {
                int row = wm * 32 + mi * 16 + (lane & 15);
                int ch = ks * 2 + (lane >> 4);
                LDSM4(a[mi], aBase + sw_off64(row, ch));
            }
            uint32_t b[4][4];
#pragma unroll
            for (int nj = 0; nj < 4; nj++) {
                int row = wn * 64 + nj * 16 + ((lane >> 4) << 3) + (lane & 7);
                int ch = ks * 2 + ((lane >> 3) & 1);
                LDSM4(b[nj], bBase + sw_off64(row, ch));
            }
#pragma unroll
            for (int mi = 0; mi < 2; mi++)
#pragma unroll
                for (int ni = 0; ni < 8; ni++)
                    MMA16816(c[mi][ni], a[mi],
                             b[ni >> 1][(ni & 1) * 2 + 0], b[ni >> 1][(ni & 1) * 2 + 1]);
        }
    }

#pragma unroll
    for (int mi = 0; mi < 2; mi++) {
#pragma unroll
        for (int ni = 0; ni < 8; ni++) {
            int r0 = m0 + wm * 32 + mi * 16 + (lane >> 2);
            int nc = n0 + wn * 64 + ni * 8 + (lane & 3) * 2;
            float2 bvv = *(const float2*)&bias[nc];
#pragma unroll
            for (int rr = 0; rr < 2; rr++) {
                int m = r0 + rr * 8;
                *(float2*)&out[(size_t)m * NN + nc] =
                    make_float2(c[mi][ni][rr * 2 + 0] + bvv.x,
                                c[mi][ni][rr * 2 + 1] + bvv.y);
            }
        }
    }
}

// ---------------------------------------------------------------------------
// HMMA flash attention, fp16, base-2 softmax, tensor-core row sums.
// 128 q-rows/CTA, 64-key tiles, 4-stage pipeline, 80KB smem -> 2 CTA/SM.
// ---------------------------------------------------------------------------
__device__ __forceinline__ uint32_t sw_off128(int row, int ch) {
    return (uint32_t)(row * 128 + ((ch ^ (row & 7)) << 4));
}

#define ATTN_SMEM 81920
#define OFF_Q 0
#define OFF_STG 16384
#define NT (SS/64)

__global__ __launch_bounds__(256, 2) void attn_mma_kernel(
    const __half* __restrict__ Q, const __half* __restrict__ K,
    const __half* __restrict__ V, __half* __restrict__ C)
{
    extern __shared__ __align__(1024) char dsm[];
    const uint32_t sb = smem_u32(dsm);

    const int tid = threadIdx.x;
    const int lane = tid & 31;
    const int wm = tid >> 5;
    const int b = blockIdx.z, h = blockIdx.y;
    const int q0 = blockIdx.x * 128;
    const size_t base = ((size_t)b * HH + h) * SS * DKK;

    /* constant B-fragment of a virtual ones-column (n=0 of an 8-col block):
       m16n8k16 B frag: thread t holds col n = t/4 -> lanes 0..3 own n=0. */
    const uint32_t bone = (lane < 4) ? 0x3C003C00u : 0u;

    {
        uint32_t dq = sb + OFF_Q;
#pragma unroll
        for (int i = 0; i < 4; i++) {
            int id = tid + i * 256;
            int row = id >> 3, ch = id & 7;
            CPASYNC16(dq + sw_off128(row, ch), Q + base + (size_t)(q0 + row) * DKK + ch * 8);
        }
        asm volatile("cp.async.commit_group;" ::: "memory");
    }

    auto issue_kv = [&](int t) {
        uint32_t st = sb + OFF_STG + (uint32_t)(t & 3) * 16384u;
#pragma unroll
        for (int i = 0; i < 2; i++) {
            int id = tid + i * 256;
            int row = id >> 3, ch = id & 7;
            uint32_t so = sw_off128(row, ch);
            CPASYNC16(st + so,         K + base + (size_t)(t * 64 + row) * DKK + ch * 8);
            CPASYNC16(st + 8192u + so, V + base + (size_t)(t * 64 + row) * DKK + ch * 8);
        }
        asm volatile("cp.async.commit_group;" ::: "memory");
    };

    issue_kv(0);
    issue_kv(1);
    issue_kv(2);

    asm volatile("cp.async.wait_group 3;" ::: "memory");
    __syncthreads();

    uint32_t qh[4][4];
#pragma unroll
    for (int ks = 0; ks < 4; ks++) {
        int row = wm * 16 + (lane & 15);
        int ch = ks * 2 + (lane >> 4);
        LDSM4(qh[ks], sb + OFF_Q + sw_off128(row, ch));
    }

    float o[8][4];
#pragma unroll
    for (int i = 0; i < 8; i++)
#pragma unroll
        for (int j = 0; j < 4; j++) o[i][j] = 0.0f;
    float oE[4] = {0.f, 0.f, 0.f, 0.f};   /* l accumulator (ones-column) */
    float m0 = -1e30f, m1 = -1e30f;

    for (int t = 0; t < NT; t++) {
        if (t <= NT - 3)      asm volatile("cp.async.wait_group 2;" ::: "memory");
        else if (t == NT - 2) asm volatile("cp.async.wait_group 1;" ::: "memory");
        else                  asm volatile("cp.async.wait_group 0;" ::: "memory");
        __syncthreads();
        if (t + 3 < NT) issue_kv(t + 3);

        uint32_t st = sb + OFF_STG + (uint32_t)(t & 3) * 16384u;
        uint32_t kh = st, vh = st + 8192u;

        float s[8][4];
#pragma unroll
        for (int i = 0; i < 8; i++)
#pragma unroll
            for (int j = 0; j < 4; j++) s[i][j] = 0.0f;

#pragma unroll
        for (int ks = 0; ks < 4; ks++) {
#pragma unroll
            for (int nj = 0; nj < 4; nj++) {
                int row = nj * 16 + ((lane >> 4) << 3) + (lane & 7);
                int ch = ks * 2 + ((lane >> 3) & 1);
                uint32_t bh[4];
                LDSM4(bh, kh + sw_off128(row, ch));
#pragma unroll
                for (int half = 0; half < 2; half++)
                    MMA16816(s[nj * 2 + half], qh[ks], bh[half * 2], bh[half * 2 + 1]);
            }
        }

        // ---- online softmax (base-2, sums via tensor core)
        float mt0 = -1e30f, mt1 = -1e30f;
#pragma unroll
        for (int ni = 0; ni < 8; ni++) {
            mt0 = fmaxf(mt0, fmaxf(s[ni][0], s[ni][1]));
            mt1 = fmaxf(mt1, fmaxf(s[ni][2], s[ni][3]));
        }
        mt0 = fmaxf(mt0, __shfl_xor_sync(0xffffffffu, mt0, 1));
        mt0 = fmaxf(mt0, __shfl_xor_sync(0xffffffffu, mt0, 2));
        mt1 = fmaxf(mt1, __shfl_xor_sync(0xffffffffu, mt1, 1));
        mt1 = fmaxf(mt1, __shfl_xor_sync(0xffffffffu, mt1, 2));
        float mn0 = fmaxf(m0, mt0), mn1 = fmaxf(m1, mt1);
        float a0 = ex2(m0 - mn0), a1 = ex2(m1 - mn1);
#pragma unroll
        for (int ni = 0; ni < 8; ni++) {
            s[ni][0] = ex2(s[ni][0] - mn0);
            s[ni][1] = ex2(s[ni][1] - mn0);
            s[ni][2] = ex2(s[ni][2] - mn1);
            s[ni][3] = ex2(s[ni][3] - mn1);
        }
        m0 = mn0; m1 = mn1;
#pragma unroll
        for (int ni = 0; ni < 8; ni++) {
            o[ni][0] *= a0; o[ni][1] *= a0;
            o[ni][2] *= a1; o[ni][3] *= a1;
        }
        oE[0] *= a0; oE[1] *= a0; oE[2] *= a1; oE[3] *= a1;

        // ---- O += P @ V ; l += P @ ones
#pragma unroll
        for (int kb = 0; kb < 4; kb++) {
            uint32_t ph[4];
            ph[0] = pack_f16(s[2*kb][0],   s[2*kb][1]);
            ph[1] = pack_f16(s[2*kb][2],   s[2*kb][3]);
            ph[2] = pack_f16(s[2*kb+1][0], s[2*kb+1][1]);
            ph[3] = pack_f16(s[2*kb+1][2], s[2*kb+1][3]);
            MMA16816(oE, ph, bone, bone);
#pragma unroll
            for (int dj = 0; dj < 4; dj++) {
                int qm = lane >> 3;
                int row = kb * 16 + (qm & 1) * 8 + (lane & 7);
                int ch = dj * 2 + (qm >> 1);
                uint32_t vr[4];
                LDSM4T(vr, vh + sw_off128(row, ch));
#pragma unroll
                for (int half = 0; half < 2; half++)
                    MMA16816(o[dj * 2 + half], ph, vr[half * 2], vr[half * 2 + 1]);
            }
        }
    }

    /* l lives in col 0 of the oE fragment -> lanes with lane%4==0 */
    float l0 = __shfl_sync(0xffffffffu, oE[0], lane & ~3);
    float l1 = __shfl_sync(0xffffffffu, oE[2], lane & ~3);
    float inv0 = 1.0f / l0, inv1 = 1.0f / l1;
    int srow0 = q0 + wm * 16 + (lane >> 2);
#pragma unroll
    for (int ni = 0; ni < 8; ni++) {
        int d = ni * 8 + (lane & 3) * 2;
        size_t i0 = ((size_t)b * SS + srow0) * NN + h * DKK + d;
        size_t i1 = ((size_t)b * SS + srow0 + 8) * NN + h * DKK + d;
        *(uint32_t*)&C[i0] = pack_f16(o[ni][0] * inv0, o[ni][1] * inv0);
        *(uint32_t*)&C[i1] = pack_f16(o[ni][2] * inv1, o[ni][3] * inv1);
    }
}

// ---------------------------------------------------------------------------
extern "C" void kernel_launch(void* const* d_in, const int* in_sizes, int n_in,
                              void* d_out, int out_size)
{
    const float* x  = (const float*)d_in[0];
    const float* Wq = (const float*)d_in[1];
    const float* bq = (const float*)d_in[2];
    const float* Wk = (const float*)d_in[3];
    const float* bk = (const float*)d_in[4];
    const float* Wv = (const float*)d_in[5];
    const float* bv = (const float*)d_in[6];
    const float* Wo = (const float*)d_in[7];
    const float* bo = (const float*)d_in[8];
    float* out = (float*)d_out;

    __half *q, *k, *v, *xh, *c, *wt;
    cudaGetSymbolAddress((void**)&q, g_q);
    cudaGetSymbolAddress((void**)&k, g_k);
    cudaGetSymbolAddress((void**)&v, g_v);
    cudaGetSymbolAddress((void**)&xh, g_x);
    cudaGetSymbolAddress((void**)&c, g_c);
    cudaGetSymbolAddress((void**)&wt, g_wt);

    cudaFuncSetAttribute(attn_mma_kernel, cudaFuncAttributeMaxDynamicSharedMemorySize, ATTN_SMEM);

    tof16_kernel<<<(MM * KK / 4 + 255) / 256, 256>>>(x, xh, MM * KK / 4);

    transpose_all_kernel<<<dim3(32, 32, 4), dim3(32, 8)>>>(Wq, Wk, Wv, Wo, wt);

    gemm_qkv_kernel<<<dim3(32, 64), 256>>>(xh, wt, bq, bk, bv, q, k, v);

    attn_mma_kernel<<<dim3(SS / 128, HH, BB), 256, ATTN_SMEM>>>(q, k, v, c);

    gemm_out_kernel<<<dim3(8, 64), 256>>>(c, wt + 3 * WSZc, bo, out);
}